// round 13
// baseline (speedup 1.0000x reference)
#include <cuda_runtime.h>
#include <cuda_fp16.h>
#include <math_constants.h>
#include <cstdint>

#define N_POS 3136
#define HW    56
#define MIDC  32
#define HEADS 8
#define INV   0.125f   // 1/sqrt(64)
#define LOG2E 1.4426950408889634f
#define NSPLIT 4       // key-splits: 4 x 784 keys (7 chunks of 112)

// ---------------- scratch (global, no allocation in kernel_launch) ----------
__device__ float  g_q [HEADS * N_POS * MIDC];   // [h][p][m] fp32
__device__ __half g_k [HEADS * N_POS * MIDC];   // [h][p][m] fp16
__device__ __half g_vT[HEADS * MIDC * N_POS];   // [h][m][p] fp16 (transposed V)
__device__ __half g_rowb[HEADS * N_POS * HW];   // log2e*inv-scaled row bias (f16)
__device__ __half g_colb[HEADS * N_POS * HW];   // log2e*inv-scaled col bias (f16)
__device__ float g_oP [NSPLIT][MIDC * HEADS * N_POS];  // partial O (unnormalized)
__device__ float g_lsP[NSPLIT][HEADS * N_POS];         // partial lsum

// ---------------- helpers ----------------------------------------------------
__device__ __forceinline__ uint32_t pkh2(float lo, float hi) {
    uint32_t r;
    asm("cvt.rn.f16x2.f32 %0, %1, %2;" : "=r"(r) : "f"(hi), "f"(lo));
    return r;
}
__device__ __forceinline__ uint32_t ex2h2(uint32_t x) {
    uint32_t r; asm("ex2.approx.f16x2 %0, %1;" : "=r"(r) : "r"(x)); return r;
}
__device__ __forceinline__ uint32_t haddu2(uint32_t a, uint32_t b) {
    uint32_t r; asm("add.rn.f16x2 %0, %1, %2;" : "=r"(r) : "r"(a), "r"(b)); return r;
}
// f32-accumulator MMA (PV)
__device__ __forceinline__ void mma_f16(
    float& d0, float& d1, float& d2, float& d3,
    uint32_t a0, uint32_t a1, uint32_t a2, uint32_t a3,
    uint32_t b0, uint32_t b1)
{
    asm("mma.sync.aligned.m16n8k16.row.col.f32.f16.f16.f32 "
        "{%0,%1,%2,%3}, {%4,%5,%6,%7}, {%8,%9}, {%0,%1,%2,%3};"
        : "+f"(d0), "+f"(d1), "+f"(d2), "+f"(d3)
        : "r"(a0), "r"(a1), "r"(a2), "r"(a3), "r"(b0), "r"(b1));
}
// f16-accumulator MMA (S): D/C are 2 x f16x2
__device__ __forceinline__ void mma_f16acc(
    uint32_t& d0, uint32_t& d1,
    uint32_t a0, uint32_t a1, uint32_t a2, uint32_t a3,
    uint32_t b0, uint32_t b1)
{
    asm("mma.sync.aligned.m16n8k16.row.col.f16.f16.f16.f16 "
        "{%0,%1}, {%2,%3,%4,%5}, {%6,%7}, {%0,%1};"
        : "+r"(d0), "+r"(d1)
        : "r"(a0), "r"(a1), "r"(a2), "r"(a3), "r"(b0), "r"(b1));
}

#define CP_ASYNC16(dst_smem, src) \
    asm volatile("cp.async.cg.shared.global [%0], [%1], 16;" \
                 :: "r"((unsigned)(dst_smem)), "l"(src))
#define CP_COMMIT()  asm volatile("cp.async.commit_group;")
#define CP_WAIT0()   asm volatile("cp.async.wait_group 0;" ::: "memory")

// ---------------- Kernel 1: fused QKV projection ----------------------------
__global__ __launch_bounds__(256) void qkv_kernel(
    const float* __restrict__ x,
    const float* __restrict__ Wq, const float* __restrict__ bq,
    const float* __restrict__ Wk, const float* __restrict__ bk,
    const float* __restrict__ Wv, const float* __restrict__ bv)
{
    __shared__ float Xs[64 * 64];
    __shared__ float Ws[64 * 68];

    const int p0  = blockIdx.x * 64;
    const int by  = blockIdx.y;
    const int mat = by >> 2;
    const int dl0 = (by & 3) * 64;
    const float* W    = (mat == 0) ? Wq : (mat == 1) ? Wk : Wv;
    const float* bias = (mat == 0) ? bq : (mat == 1) ? bk : bv;

    const int tid = threadIdx.x;
    for (int i = tid; i < 64 * 16; i += 256) {
        int r = i >> 4, c4 = (i & 15) * 4;
        *(float4*)&Xs[r * 64 + c4] = *(const float4*)&x[r * N_POS + p0 + c4];
        *(float4*)&Ws[r * 68 + c4] = *(const float4*)&W[(dl0 + r) * 64 + c4];
    }
    __syncthreads();

    const int tx = tid & 15, ty = tid >> 4;
    float acc[4][4];
#pragma unroll
    for (int i = 0; i < 4; i++)
#pragma unroll
        for (int j = 0; j < 4; j++) acc[i][j] = 0.f;

#pragma unroll 8
    for (int kk = 0; kk < 64; kk++) {
        float a[4];
#pragma unroll
        for (int i = 0; i < 4; i++) a[i] = Ws[(ty * 4 + i) * 68 + kk];
        float4 b = *(const float4*)&Xs[kk * 64 + tx * 4];
#pragma unroll
        for (int i = 0; i < 4; i++) {
            acc[i][0] += a[i] * b.x; acc[i][1] += a[i] * b.y;
            acc[i][2] += a[i] * b.z; acc[i][3] += a[i] * b.w;
        }
    }

#pragma unroll
    for (int i = 0; i < 4; i++) {
        int d = dl0 + ty * 4 + i;
        float bv_ = bias[d];
        int h = d & 7, m = d >> 3;
#pragma unroll
        for (int j = 0; j < 4; j++) {
            int p = p0 + tx * 4 + j;
            float val = acc[i][j] + bv_;
            if (mat == 0)      g_q [(h * N_POS + p) * MIDC + m] = val;
            else if (mat == 1) g_k [(h * N_POS + p) * MIDC + m] = __float2half(val);
            else               g_vT[(h * MIDC + m) * N_POS + p] = __float2half(val);
        }
    }
}

// ---------------- Kernel 2: bias precompute (x INV*LOG2E, f16 out) ----------
__global__ __launch_bounds__(256) void bias_kernel(
    const float* __restrict__ rowT, const float* __restrict__ colT)
{
    int idx = blockIdx.x * 256 + threadIdx.x;
    int h   = idx / (N_POS * 112);
    int rem = idx - h * (N_POS * 112);
    int p   = rem / 112;
    int t   = rem - p * 112;
    const float* Qp = &g_q[(h * N_POS + p) * MIDC];
    const float sc = INV * LOG2E;

    if (t < HW) {
        int i = p / HW;
        const float* tr = &rowT[(t - i + 55) * 16];
        float acc = 0.f;
#pragma unroll
        for (int m = 0; m < 16; m++) acc += Qp[m] * tr[m];
        g_rowb[(h * N_POS + p) * HW + t] = __float2half(acc * sc);
    } else {
        int l = t - HW, j = p % HW;
        const float* tc = &colT[(l - j + 55) * 16];
        float acc = 0.f;
#pragma unroll
        for (int m = 0; m < 16; m++) acc += Qp[16 + m] * tc[m];
        g_colb[(h * N_POS + p) * HW + l] = __float2half(acc * sc);
    }
}

// ---------------- Kernel 3: fp16 flash attention, key-split x4 --------------
// 1568 blocks = 8 heads x 49 q-tiles x 4 key-quarters; 128 threads = 4 warps.
// Each block: 7 chunks of 112 keys; writes unnormalized O partial + lsum.
// smem (bytes):
//   K0 @0      : [112 keys][40 halves] (80B rows, 20-word stride)
//   K1 @8960
//   V0 @17920  : [32 ch][136 halves]   (272B rows, 68-word stride)
//   V1 @26624
//   Pm @35328  : [64 q][136 halves]    (68-word stride)
#define KOFF0 0
#define KOFF1 8960
#define VOFF0 17920
#define VOFF1 26624
#define PMOFF 35328
#define SMEMB 52736          // 4 blocks/SM

__global__ __launch_bounds__(128, 4) void attn_kernel()
{
    extern __shared__ char smc[];

    const int bx  = blockIdx.x;
    const int h   = bx / 196;
    const int rem = bx - h * 196;
    const int qt  = rem >> 2;
    const int s   = rem & 3;
    const int p0  = qt * 64;
    const int cbeg = s * 7, cend = cbeg + 7;

    const int tid = threadIdx.x;
    const int w   = tid >> 5;
    const int ln  = tid & 31;
    const int g   = ln >> 2;          // 0..7
    const int t   = ln & 3;           // 0..3
    const int wq0 = w * 16;
    const int hbase = h * N_POS;

    const unsigned sm_u32 = (unsigned)__cvta_generic_to_shared(smc);

    // ---- Q fragments (x INV*LOG2E) as packed fp16 -------------------------
    uint32_t qa[2][4];
    {
        const float sc = INV * LOG2E;
        const float* Q0 = &g_q[(hbase + p0 + wq0 + g) * MIDC];
        const float* Q8 = Q0 + 8 * MIDC;
#pragma unroll
        for (int kc = 0; kc < 2; kc++) {
            int c0 = 16 * kc + 2 * t;
            qa[kc][0] = pkh2(Q0[c0]     * sc, Q0[c0 + 1] * sc);
            qa[kc][1] = pkh2(Q8[c0]     * sc, Q8[c0 + 1] * sc);
            qa[kc][2] = pkh2(Q0[c0 + 8] * sc, Q0[c0 + 9] * sc);
            qa[kc][3] = pkh2(Q8[c0 + 8] * sc, Q8[c0 + 9] * sc);
        }
    }

    // ---- column-bias as packed f16x2 pairs (rows g and g+8) ---------------
    uint32_t cb2g[7], cb2g8[7];
    {
        const __half* C0 = &g_colb[(hbase + p0 + wq0 + g) * HW];
        const __half* C8 = C0 + 8 * HW;
#pragma unroll
        for (int nt = 0; nt < 7; nt++) {
            int c0 = 8 * nt + 2 * t;
            cb2g[nt]  = *(const uint32_t*)(C0 + c0);
            cb2g8[nt] = *(const uint32_t*)(C8 + c0);
        }
    }

    // ---- rb via gmem, prefetched one iteration ahead ----------------------
    const __half* rbg  = g_rowb + (hbase + p0 + wq0 + g) * HW;
    const __half* rbg8 = rbg + 8 * HW;
    uint32_t rbnx0 = *(const uint32_t*)(rbg  + 2 * cbeg);   // kr pair (2c, 2c+1)
    uint32_t rbnx8 = *(const uint32_t*)(rbg8 + 2 * cbeg);

    float Oa[4][4];
#pragma unroll
    for (int mt = 0; mt < 4; mt++)
#pragma unroll
        for (int j = 0; j < 4; j++) Oa[mt][j] = 0.f;
    float lsum0 = 0.f, lsum1 = 0.f;

    // ---- async tile loader: K 448x16B + V^T 448x16B -----------------------
    auto load_tile = [&](int c, int buf) {
        const uint32_t kof = sm_u32 + (buf ? KOFF1 : KOFF0);
        const uint32_t vof = sm_u32 + (buf ? VOFF1 : VOFF0);
        const __half* Kg = g_k  + (hbase + c * 112) * MIDC;
        const __half* Vg = g_vT + h * MIDC * N_POS + c * 112;
#pragma unroll 7
        for (int i = tid; i < 896; i += 128) {
            if (i < 448) {
                int r = i >> 2, cc = i & 3;
                CP_ASYNC16(kof + r * 80 + cc * 16, Kg + r * 32 + cc * 8);
            } else {
                int j = i - 448;
                int m = j / 14, t14 = j - m * 14;
                CP_ASYNC16(vof + m * 272 + t14 * 16, Vg + m * N_POS + t14 * 8);
            }
        }
        CP_COMMIT();
    };

    load_tile(cbeg, cbeg & 1);

    for (int c = cbeg; c < cend; c++) {
        const int buf = c & 1;
        CP_WAIT0();
        __syncthreads();
        if (c + 1 < cend) load_tile(c + 1, (c + 1) & 1);

        const uint32_t* Ku = (const uint32_t*)(smc + (buf ? KOFF1 : KOFF0));
        const uint32_t* Vw = (const uint32_t*)(smc + (buf ? VOFF1 : VOFF0));
        uint32_t* Pw = (uint32_t*)(smc + PMOFF);

        // current rb pair; prefetch next
        uint32_t rbc0 = rbnx0, rbc8 = rbnx8;
        if (c + 1 < cend) {
            rbnx0 = *(const uint32_t*)(rbg  + 2 * (c + 1));
            rbnx8 = *(const uint32_t*)(rbg8 + 2 * (c + 1));
        }
        uint32_t r2[2][2];
        {
            __half2 a = *(__half2*)&rbc0, b = *(__half2*)&rbc8;
            __half2 t00 = __half2half2(__low2half(a)),  t10 = __half2half2(__high2half(a));
            __half2 t01 = __half2half2(__low2half(b)),  t11 = __half2half2(__high2half(b));
            r2[0][0] = *(uint32_t*)&t00; r2[1][0] = *(uint32_t*)&t10;
            r2[0][1] = *(uint32_t*)&t01; r2[1][1] = *(uint32_t*)&t11;
        }

        uint32_t ls2g = 0u, ls2g8 = 0u;   // f16x2 zero

        // ---- S = Q K^T (f16 acc, bias as C); P = ex2.f16x2 ---------------
#pragma unroll
        for (int nt = 0; nt < 14; nt++) {
            const int sel = (nt < 7) ? 0 : 1;
            const int ci  = (nt < 7) ? nt : nt - 7;
            const uint32_t* krow = Ku + (8 * nt + g) * 20 + t;
            uint32_t b00 = krow[0], b01 = krow[4], b10 = krow[8], b11 = krow[12];
            uint32_t d0 = haddu2(r2[sel][0], cb2g[ci]);
            uint32_t d1 = haddu2(r2[sel][1], cb2g8[ci]);
            mma_f16acc(d0, d1, qa[0][0], qa[0][1], qa[0][2], qa[0][3], b00, b01);
            mma_f16acc(d0, d1, qa[1][0], qa[1][1], qa[1][2], qa[1][3], b10, b11);
            uint32_t e0 = ex2h2(d0);
            uint32_t e1 = ex2h2(d1);
            ls2g  = haddu2(ls2g,  e0);
            ls2g8 = haddu2(ls2g8, e1);
            Pw[(wq0 + g)     * 68 + 4 * nt + t] = e0;
            Pw[(wq0 + g + 8) * 68 + 4 * nt + t] = e1;
        }
        {
            __half2 a = *(__half2*)&ls2g, b = *(__half2*)&ls2g8;
            lsum0 += __low2float(a) + __high2float(a);
            lsum1 += __low2float(b) + __high2float(b);
        }

        __syncwarp();

        // ---- O += P V  (7 exact k16 chunks over 112 keys) -----------------
#pragma unroll
        for (int kc = 0; kc < 7; kc++) {
            const uint32_t* pr0 = Pw + (wq0 + g)     * 68 + 8 * kc + t;
            const uint32_t* pr8 = Pw + (wq0 + g + 8) * 68 + 8 * kc + t;
            uint32_t a0 = pr0[0], a1 = pr8[0], a2 = pr0[4], a3 = pr8[4];
#pragma unroll
            for (int mt = 0; mt < 4; mt++) {
                const uint32_t* vrow = Vw + (8 * mt + g) * 68 + 8 * kc + t;
                mma_f16(Oa[mt][0], Oa[mt][1], Oa[mt][2], Oa[mt][3],
                        a0, a1, a2, a3, vrow[0], vrow[4]);
            }
        }
    }

    // ---- reduce lsum over group, store partials ---------------------------
    lsum0 += __shfl_xor_sync(0xffffffffu, lsum0, 1);
    lsum0 += __shfl_xor_sync(0xffffffffu, lsum0, 2);
    lsum1 += __shfl_xor_sync(0xffffffffu, lsum1, 1);
    lsum1 += __shfl_xor_sync(0xffffffffu, lsum1, 2);

    float* Op = g_oP[s];
    float* Lp = g_lsP[s];
    const int pA = p0 + wq0 + g;
    if (t == 0) {
        Lp[h * N_POS + pA]     = lsum0;
        Lp[h * N_POS + pA + 8] = lsum1;
    }
#pragma unroll
    for (int mt = 0; mt < 4; mt++) {
        int c0 = 8 * mt + 2 * t;
        Op[(c0       * HEADS + h) * N_POS + pA]     = Oa[mt][0];
        Op[((c0 + 1) * HEADS + h) * N_POS + pA]     = Oa[mt][1];
        Op[(c0       * HEADS + h) * N_POS + pA + 8] = Oa[mt][2];
        Op[((c0 + 1) * HEADS + h) * N_POS + pA + 8] = Oa[mt][3];
    }
}

// ---------------- Kernel 4: combine + output projection (1 thread/output) ---
// 784 blocks x 256 threads; block covers 4 positions x all 64 out-channels.
__global__ __launch_bounds__(256) void out_kernel(
    const float* __restrict__ Wo, const float* __restrict__ bo,
    float* __restrict__ out)
{
    __shared__ float rinvs[32];      // [h*4 + pj]
    __shared__ float Xs[256 * 4];    // [k][pj]

    const int p0  = blockIdx.x * 4;
    const int tid = threadIdx.x;

    if (tid < 32) {
        int hh = tid >> 2, j = tid & 3;
        int ix = hh * N_POS + p0 + j;
        float l = g_lsP[0][ix] + g_lsP[1][ix] + g_lsP[2][ix] + g_lsP[3][ix];
        rinvs[tid] = 1.0f / l;
    }
    __syncthreads();

#pragma unroll
    for (int r = 0; r < 4; r++) {
        int idx = tid + 256 * r;
        int k = idx >> 2, j = idx & 3;
        int ix = k * N_POS + p0 + j;
        float v = g_oP[0][ix] + g_oP[1][ix] + g_oP[2][ix] + g_oP[3][ix];
        Xs[k * 4 + j] = v * rinvs[(k & 7) * 4 + j];
    }
    __syncthreads();

    const int co = tid >> 2;         // 0..63
    const int pj = tid & 3;          // 0..3
    const float4* wrow = (const float4*)(Wo + co * 256);
    float acc = 0.f;
#pragma unroll 8
    for (int k4 = 0; k4 < 64; k4++) {
        float4 wv = wrow[k4];
        acc += wv.x * Xs[(k4 * 4 + 0) * 4 + pj];
        acc += wv.y * Xs[(k4 * 4 + 1) * 4 + pj];
        acc += wv.z * Xs[(k4 * 4 + 2) * 4 + pj];
        acc += wv.w * Xs[(k4 * 4 + 3) * 4 + pj];
    }
    out[co * N_POS + p0 + pj] = acc + bo[co];
}

// ---------------- launch -----------------------------------------------------
extern "C" void kernel_launch(void* const* d_in, const int* in_sizes, int n_in,
                              void* d_out, int out_size)
{
    const float* x    = (const float*)d_in[0];
    const float* Wq   = (const float*)d_in[1];
    const float* bq   = (const float*)d_in[2];
    const float* Wk   = (const float*)d_in[3];
    const float* bk   = (const float*)d_in[4];
    const float* Wv   = (const float*)d_in[5];
    const float* bv   = (const float*)d_in[6];
    const float* Wo   = (const float*)d_in[7];
    const float* bo   = (const float*)d_in[8];
    const float* rowT = (const float*)d_in[9];
    const float* colT = (const float*)d_in[10];

    cudaFuncSetAttribute(attn_kernel,
                         cudaFuncAttributeMaxDynamicSharedMemorySize, SMEMB);

    qkv_kernel<<<dim3(49, 12), 256>>>(x, Wq, bq, Wk, bk, Wv, bv);
    bias_kernel<<<10976, 256>>>(rowT, colT);
    attn_kernel<<<1568, 128, SMEMB>>>();
    out_kernel<<<784, 256>>>(Wo, bo, (float*)d_out);
}

// round 14
// speedup vs baseline: 1.0884x; 1.0884x over previous
#include <cuda_runtime.h>
#include <cuda_fp16.h>
#include <math_constants.h>
#include <cstdint>

#define N_POS 3136
#define HW    56
#define MIDC  32
#define HEADS 8
#define INV   0.125f   // 1/sqrt(64)
#define LOG2E 1.4426950408889634f
#define NCH   28       // 28 chunks of 112 keys (full 3136 per block)

// ---------------- scratch (global, no allocation in kernel_launch) ----------
__device__ float  g_q [HEADS * N_POS * MIDC];   // [h][p][m] fp32
__device__ __half g_k [HEADS * N_POS * MIDC];   // [h][p][m] fp16
__device__ __half g_vT[HEADS * MIDC * N_POS];   // [h][m][p] fp16 (transposed V)
__device__ __half g_rowb[HEADS * N_POS * HW];   // log2e*inv-scaled row bias (f16)
__device__ __half g_colb[HEADS * N_POS * HW];   // log2e*inv-scaled col bias (f16)
__device__ float g_y[HEADS * 64 * N_POS];       // per-head projected output Y_h

// ---------------- helpers ----------------------------------------------------
__device__ __forceinline__ uint32_t pkh2(float lo, float hi) {
    uint32_t r;
    asm("cvt.rn.f16x2.f32 %0, %1, %2;" : "=r"(r) : "f"(hi), "f"(lo));
    return r;
}
__device__ __forceinline__ uint32_t ex2h2(uint32_t x) {
    uint32_t r; asm("ex2.approx.f16x2 %0, %1;" : "=r"(r) : "r"(x)); return r;
}
__device__ __forceinline__ uint32_t haddu2(uint32_t a, uint32_t b) {
    uint32_t r; asm("add.rn.f16x2 %0, %1, %2;" : "=r"(r) : "r"(a), "r"(b)); return r;
}
// f32-accumulator MMA
__device__ __forceinline__ void mma_f16(
    float& d0, float& d1, float& d2, float& d3,
    uint32_t a0, uint32_t a1, uint32_t a2, uint32_t a3,
    uint32_t b0, uint32_t b1)
{
    asm("mma.sync.aligned.m16n8k16.row.col.f32.f16.f16.f32 "
        "{%0,%1,%2,%3}, {%4,%5,%6,%7}, {%8,%9}, {%0,%1,%2,%3};"
        : "+f"(d0), "+f"(d1), "+f"(d2), "+f"(d3)
        : "r"(a0), "r"(a1), "r"(a2), "r"(a3), "r"(b0), "r"(b1));
}
// f16-accumulator MMA (S phase)
__device__ __forceinline__ void mma_f16acc(
    uint32_t& d0, uint32_t& d1,
    uint32_t a0, uint32_t a1, uint32_t a2, uint32_t a3,
    uint32_t b0, uint32_t b1)
{
    asm("mma.sync.aligned.m16n8k16.row.col.f16.f16.f16.f16 "
        "{%0,%1}, {%2,%3,%4,%5}, {%6,%7}, {%0,%1};"
        : "+r"(d0), "+r"(d1)
        : "r"(a0), "r"(a1), "r"(a2), "r"(a3), "r"(b0), "r"(b1));
}

#define CP_ASYNC16(dst_smem, src) \
    asm volatile("cp.async.cg.shared.global [%0], [%1], 16;" \
                 :: "r"((unsigned)(dst_smem)), "l"(src))
#define CP_COMMIT()  asm volatile("cp.async.commit_group;")
#define CP_WAIT0()   asm volatile("cp.async.wait_group 0;" ::: "memory")

// ---------------- Kernel 1: fused QKV projection ----------------------------
__global__ __launch_bounds__(256) void qkv_kernel(
    const float* __restrict__ x,
    const float* __restrict__ Wq, const float* __restrict__ bq,
    const float* __restrict__ Wk, const float* __restrict__ bk,
    const float* __restrict__ Wv, const float* __restrict__ bv)
{
    __shared__ float Xs[64 * 64];
    __shared__ float Ws[64 * 68];

    const int p0  = blockIdx.x * 64;
    const int by  = blockIdx.y;
    const int mat = by >> 2;
    const int dl0 = (by & 3) * 64;
    const float* W    = (mat == 0) ? Wq : (mat == 1) ? Wk : Wv;
    const float* bias = (mat == 0) ? bq : (mat == 1) ? bk : bv;

    const int tid = threadIdx.x;
    for (int i = tid; i < 64 * 16; i += 256) {
        int r = i >> 4, c4 = (i & 15) * 4;
        *(float4*)&Xs[r * 64 + c4] = *(const float4*)&x[r * N_POS + p0 + c4];
        *(float4*)&Ws[r * 68 + c4] = *(const float4*)&W[(dl0 + r) * 64 + c4];
    }
    __syncthreads();

    const int tx = tid & 15, ty = tid >> 4;
    float acc[4][4];
#pragma unroll
    for (int i = 0; i < 4; i++)
#pragma unroll
        for (int j = 0; j < 4; j++) acc[i][j] = 0.f;

#pragma unroll 8
    for (int kk = 0; kk < 64; kk++) {
        float a[4];
#pragma unroll
        for (int i = 0; i < 4; i++) a[i] = Ws[(ty * 4 + i) * 68 + kk];
        float4 b = *(const float4*)&Xs[kk * 64 + tx * 4];
#pragma unroll
        for (int i = 0; i < 4; i++) {
            acc[i][0] += a[i] * b.x; acc[i][1] += a[i] * b.y;
            acc[i][2] += a[i] * b.z; acc[i][3] += a[i] * b.w;
        }
    }

#pragma unroll
    for (int i = 0; i < 4; i++) {
        int d = dl0 + ty * 4 + i;
        float bv_ = bias[d];
        int h = d & 7, m = d >> 3;
#pragma unroll
        for (int j = 0; j < 4; j++) {
            int p = p0 + tx * 4 + j;
            float val = acc[i][j] + bv_;
            if (mat == 0)      g_q [(h * N_POS + p) * MIDC + m] = val;
            else if (mat == 1) g_k [(h * N_POS + p) * MIDC + m] = __float2half(val);
            else               g_vT[(h * MIDC + m) * N_POS + p] = __float2half(val);
        }
    }
}

// ---------------- Kernel 2: bias precompute (x INV*LOG2E, f16 out) ----------
__global__ __launch_bounds__(256) void bias_kernel(
    const float* __restrict__ rowT, const float* __restrict__ colT)
{
    int idx = blockIdx.x * 256 + threadIdx.x;
    int h   = idx / (N_POS * 112);
    int rem = idx - h * (N_POS * 112);
    int p   = rem / 112;
    int t   = rem - p * 112;
    const float* Qp = &g_q[(h * N_POS + p) * MIDC];
    const float sc = INV * LOG2E;

    if (t < HW) {
        int i = p / HW;
        const float* tr = &rowT[(t - i + 55) * 16];
        float acc = 0.f;
#pragma unroll
        for (int m = 0; m < 16; m++) acc += Qp[m] * tr[m];
        g_rowb[(h * N_POS + p) * HW + t] = __float2half(acc * sc);
    } else {
        int l = t - HW, j = p % HW;
        const float* tc = &colT[(l - j + 55) * 16];
        float acc = 0.f;
#pragma unroll
        for (int m = 0; m < 16; m++) acc += Qp[16 + m] * tc[m];
        g_colb[(h * N_POS + p) * HW + l] = __float2half(acc * sc);
    }
}

// ---------------- Kernel 3: fp16 flash attention + fused out-projection -----
// 392 blocks = 8 heads x 49 q-tiles; 128 threads = 4 warps; full 3136 keys.
// Epilogue: O normalized in-block, Y_h = Wo_h @ (O/L) via 16 HMMAs/warp,
// STG to g_y[h]. smem (bytes):
//   K0 @0      : [112 keys][40 halves] (80B rows, 20-word stride)
//   K1 @8960
//   V0 @17920  : [32 ch][136 halves]   (272B rows, 68-word stride)
//   V1 @26624
//   Pm @35328  : [64 q][136 halves]    (68-word stride)
//     epilogue reuse: Wos @35328 (64co x 20w), Os @40448 (64p x 20w)
#define KOFF0 0
#define KOFF1 8960
#define VOFF0 17920
#define VOFF1 26624
#define PMOFF 35328
#define WOSOFF 35328
#define OSOFF  40448
#define SMEMB 52736

__global__ __launch_bounds__(128, 3) void attn_kernel(
    const float* __restrict__ Wo)
{
    extern __shared__ char smc[];

    const int bx  = blockIdx.x;
    const int h   = bx / 49;
    const int qt  = bx - h * 49;
    const int p0  = qt * 64;

    const int tid = threadIdx.x;
    const int w   = tid >> 5;
    const int ln  = tid & 31;
    const int g   = ln >> 2;          // 0..7
    const int t   = ln & 3;           // 0..3
    const int wq0 = w * 16;
    const int hbase = h * N_POS;

    const unsigned sm_u32 = (unsigned)__cvta_generic_to_shared(smc);

    // ---- Q fragments (x INV*LOG2E) as packed fp16 -------------------------
    uint32_t qa[2][4];
    {
        const float sc = INV * LOG2E;
        const float* Q0 = &g_q[(hbase + p0 + wq0 + g) * MIDC];
        const float* Q8 = Q0 + 8 * MIDC;
#pragma unroll
        for (int kc = 0; kc < 2; kc++) {
            int c0 = 16 * kc + 2 * t;
            qa[kc][0] = pkh2(Q0[c0]     * sc, Q0[c0 + 1] * sc);
            qa[kc][1] = pkh2(Q8[c0]     * sc, Q8[c0 + 1] * sc);
            qa[kc][2] = pkh2(Q0[c0 + 8] * sc, Q0[c0 + 9] * sc);
            qa[kc][3] = pkh2(Q8[c0 + 8] * sc, Q8[c0 + 9] * sc);
        }
    }

    // ---- column-bias as packed f16x2 pairs (rows g and g+8) ---------------
    uint32_t cb2g[7], cb2g8[7];
    {
        const __half* C0 = &g_colb[(hbase + p0 + wq0 + g) * HW];
        const __half* C8 = C0 + 8 * HW;
#pragma unroll
        for (int nt = 0; nt < 7; nt++) {
            int c0 = 8 * nt + 2 * t;
            cb2g[nt]  = *(const uint32_t*)(C0 + c0);
            cb2g8[nt] = *(const uint32_t*)(C8 + c0);
        }
    }

    // ---- rb via gmem, prefetched one iteration ahead ----------------------
    const __half* rbg  = g_rowb + (hbase + p0 + wq0 + g) * HW;
    const __half* rbg8 = rbg + 8 * HW;
    uint32_t rbnx0 = *(const uint32_t*)(rbg);
    uint32_t rbnx8 = *(const uint32_t*)(rbg8);

    float Oa[4][4];
#pragma unroll
    for (int mt = 0; mt < 4; mt++)
#pragma unroll
        for (int j = 0; j < 4; j++) Oa[mt][j] = 0.f;
    float lsum0 = 0.f, lsum1 = 0.f;

    // ---- async tile loader: K 448x16B + V^T 448x16B -----------------------
    auto load_tile = [&](int c, int buf) {
        const uint32_t kof = sm_u32 + (buf ? KOFF1 : KOFF0);
        const uint32_t vof = sm_u32 + (buf ? VOFF1 : VOFF0);
        const __half* Kg = g_k  + (hbase + c * 112) * MIDC;
        const __half* Vg = g_vT + h * MIDC * N_POS + c * 112;
#pragma unroll 7
        for (int i = tid; i < 896; i += 128) {
            if (i < 448) {
                int r = i >> 2, cc = i & 3;
                CP_ASYNC16(kof + r * 80 + cc * 16, Kg + r * 32 + cc * 8);
            } else {
                int j = i - 448;
                int m = j / 14, t14 = j - m * 14;
                CP_ASYNC16(vof + m * 272 + t14 * 16, Vg + m * N_POS + t14 * 8);
            }
        }
        CP_COMMIT();
    };

    load_tile(0, 0);

    for (int c = 0; c < NCH; c++) {
        const int buf = c & 1;
        CP_WAIT0();
        __syncthreads();
        if (c + 1 < NCH) load_tile(c + 1, (c + 1) & 1);

        const uint32_t* Ku = (const uint32_t*)(smc + (buf ? KOFF1 : KOFF0));
        const uint32_t* Vw = (const uint32_t*)(smc + (buf ? VOFF1 : VOFF0));
        uint32_t* Pw = (uint32_t*)(smc + PMOFF);

        // current rb pair; prefetch next
        uint32_t rbc0 = rbnx0, rbc8 = rbnx8;
        if (c + 1 < NCH) {
            rbnx0 = *(const uint32_t*)(rbg  + 2 * (c + 1));
            rbnx8 = *(const uint32_t*)(rbg8 + 2 * (c + 1));
        }
        uint32_t r2[2][2];
        {
            __half2 a = *(__half2*)&rbc0, b = *(__half2*)&rbc8;
            __half2 t00 = __half2half2(__low2half(a)),  t10 = __half2half2(__high2half(a));
            __half2 t01 = __half2half2(__low2half(b)),  t11 = __half2half2(__high2half(b));
            r2[0][0] = *(uint32_t*)&t00; r2[1][0] = *(uint32_t*)&t10;
            r2[0][1] = *(uint32_t*)&t01; r2[1][1] = *(uint32_t*)&t11;
        }

        uint32_t ls2g = 0u, ls2g8 = 0u;

        // ---- S = Q K^T (f16 acc, bias as C); P = ex2.f16x2 ---------------
#pragma unroll
        for (int nt = 0; nt < 14; nt++) {
            const int sel = (nt < 7) ? 0 : 1;
            const int ci  = (nt < 7) ? nt : nt - 7;
            const uint32_t* krow = Ku + (8 * nt + g) * 20 + t;
            uint32_t b00 = krow[0], b01 = krow[4], b10 = krow[8], b11 = krow[12];
            uint32_t d0 = haddu2(r2[sel][0], cb2g[ci]);
            uint32_t d1 = haddu2(r2[sel][1], cb2g8[ci]);
            mma_f16acc(d0, d1, qa[0][0], qa[0][1], qa[0][2], qa[0][3], b00, b01);
            mma_f16acc(d0, d1, qa[1][0], qa[1][1], qa[1][2], qa[1][3], b10, b11);
            uint32_t e0 = ex2h2(d0);
            uint32_t e1 = ex2h2(d1);
            ls2g  = haddu2(ls2g,  e0);
            ls2g8 = haddu2(ls2g8, e1);
            Pw[(wq0 + g)     * 68 + 4 * nt + t] = e0;
            Pw[(wq0 + g + 8) * 68 + 4 * nt + t] = e1;
        }
        {
            __half2 a = *(__half2*)&ls2g, b = *(__half2*)&ls2g8;
            lsum0 += __low2float(a) + __high2float(a);
            lsum1 += __low2float(b) + __high2float(b);
        }

        __syncwarp();

        // ---- O += P V  (7 exact k16 chunks over 112 keys) -----------------
#pragma unroll
        for (int kc = 0; kc < 7; kc++) {
            const uint32_t* pr0 = Pw + (wq0 + g)     * 68 + 8 * kc + t;
            const uint32_t* pr8 = Pw + (wq0 + g + 8) * 68 + 8 * kc + t;
            uint32_t a0 = pr0[0], a1 = pr8[0], a2 = pr0[4], a3 = pr8[4];
#pragma unroll
            for (int mt = 0; mt < 4; mt++) {
                const uint32_t* vrow = Vw + (8 * mt + g) * 68 + 8 * kc + t;
                mma_f16(Oa[mt][0], Oa[mt][1], Oa[mt][2], Oa[mt][3],
                        a0, a1, a2, a3, vrow[0], vrow[4]);
            }
        }
    }

    // ---- epilogue: normalize, project through Wo_h, store Y_h -------------
    lsum0 += __shfl_xor_sync(0xffffffffu, lsum0, 1);
    lsum0 += __shfl_xor_sync(0xffffffffu, lsum0, 2);
    lsum1 += __shfl_xor_sync(0xffffffffu, lsum1, 1);
    lsum1 += __shfl_xor_sync(0xffffffffu, lsum1, 2);
    const float rinv0 = 1.0f / lsum0;
    const float rinv1 = 1.0f / lsum1;

    __syncthreads();                    // all warps done reading Pm region

    // stage normalized O as f16 [p 64][m 32], stride 20 words
    {
        uint32_t* Os = (uint32_t*)(smc + OSOFF);
#pragma unroll
        for (int mt = 0; mt < 4; mt++) {
            uint32_t lo = pkh2(Oa[mt][0] * rinv0, Oa[mt][1] * rinv0);
            uint32_t hi = pkh2(Oa[mt][2] * rinv1, Oa[mt][3] * rinv1);
            Os[(wq0 + g)     * 20 + 4 * mt + t] = lo;
            Os[(wq0 + g + 8) * 20 + 4 * mt + t] = hi;
        }
    }
    // stage Wo_h as f16 [co 64][m 32], stride 20 words
    {
        __half* Wos = (__half*)(smc + WOSOFF);
        for (int i = tid; i < 2048; i += 128) {
            int co = i >> 5, m = i & 31;
            Wos[co * 40 + m] = __float2half(Wo[co * 256 + m * 8 + h]);
        }
    }
    __syncthreads();

    // Y[co 16/warp][p 64] = Wo_h @ O   (A-frag = Q pattern, B-frag = K pattern)
    {
        const int wco = w * 16;
        const uint32_t* Ww = (const uint32_t*)(smc + WOSOFF);
        const uint32_t* Os = (const uint32_t*)(smc + OSOFF);
        uint32_t wa[2][4];
#pragma unroll
        for (int kc = 0; kc < 2; kc++) {
            wa[kc][0] = Ww[(wco + g)     * 20 + 8 * kc + t];
            wa[kc][1] = Ww[(wco + g + 8) * 20 + 8 * kc + t];
            wa[kc][2] = Ww[(wco + g)     * 20 + 8 * kc + t + 4];
            wa[kc][3] = Ww[(wco + g + 8) * 20 + 8 * kc + t + 4];
        }
#pragma unroll
        for (int nt = 0; nt < 8; nt++) {
            const uint32_t* orow = Os + (8 * nt + g) * 20 + t;
            uint32_t b00 = orow[0], b01 = orow[4], b10 = orow[8], b11 = orow[12];
            float y0 = 0.f, y1 = 0.f, y2 = 0.f, y3 = 0.f;
            mma_f16(y0, y1, y2, y3, wa[0][0], wa[0][1], wa[0][2], wa[0][3], b00, b01);
            mma_f16(y0, y1, y2, y3, wa[1][0], wa[1][1], wa[1][2], wa[1][3], b10, b11);
            int co = wco + g;
            int pp = p0 + 8 * nt + 2 * t;
            *(float2*)&g_y[(h * 64 + co)     * N_POS + pp] = make_float2(y0, y1);
            *(float2*)&g_y[(h * 64 + co + 8) * N_POS + pp] = make_float2(y2, y3);
        }
    }
}

// ---------------- Kernel 4: sum heads + bias --------------------------------
// 196 blocks x 256 threads; one float4 of output per thread.
__global__ __launch_bounds__(256) void sum_kernel(
    const float* __restrict__ bo, float* __restrict__ out)
{
    int idx = blockIdx.x * 256 + threadIdx.x;   // 0..50175
    int co  = idx / 784;
    int pw  = idx - co * 784;
    int p4  = pw * 4;
    float b = bo[co];
    float4 s = make_float4(b, b, b, b);
#pragma unroll
    for (int h = 0; h < HEADS; h++) {
        float4 v = *(const float4*)&g_y[(h * 64 + co) * N_POS + p4];
        s.x += v.x; s.y += v.y; s.z += v.z; s.w += v.w;
    }
    *(float4*)&out[co * N_POS + p4] = s;
}

// ---------------- launch -----------------------------------------------------
extern "C" void kernel_launch(void* const* d_in, const int* in_sizes, int n_in,
                              void* d_out, int out_size)
{
    const float* x    = (const float*)d_in[0];
    const float* Wq   = (const float*)d_in[1];
    const float* bq   = (const float*)d_in[2];
    const float* Wk   = (const float*)d_in[3];
    const float* bk   = (const float*)d_in[4];
    const float* Wv   = (const float*)d_in[5];
    const float* bv   = (const float*)d_in[6];
    const float* Wo   = (const float*)d_in[7];
    const float* bo   = (const float*)d_in[8];
    const float* rowT = (const float*)d_in[9];
    const float* colT = (const float*)d_in[10];

    cudaFuncSetAttribute(attn_kernel,
                         cudaFuncAttributeMaxDynamicSharedMemorySize, SMEMB);

    qkv_kernel<<<dim3(49, 12), 256>>>(x, Wq, bq, Wk, bk, Wv, bv);
    bias_kernel<<<10976, 256>>>(rowT, colT);
    attn_kernel<<<392, 128, SMEMB>>>(Wo);
    sum_kernel<<<196, 256>>>(bo, (float*)d_out);
}

// round 15
// speedup vs baseline: 1.6226x; 1.4908x over previous
#include <cuda_runtime.h>
#include <cuda_fp16.h>
#include <math_constants.h>
#include <cstdint>

#define N_POS 3136
#define HW    56
#define MIDC  32
#define HEADS 8
#define INV   0.125f   // 1/sqrt(64)
#define LOG2E 1.4426950408889634f
#define NCH   28       // 28 chunks of 112 keys (full 3136 per block)

// ---------------- scratch (global, no allocation in kernel_launch) ----------
__device__ float  g_q [HEADS * N_POS * MIDC];   // [h][p][m] fp32
__device__ __half g_k [HEADS * N_POS * MIDC];   // [h][p][m] fp16
__device__ __half g_vT[HEADS * MIDC * N_POS];   // [h][m][p] fp16 (transposed V)
__device__ __half g_rowb[HEADS * N_POS * HW];   // log2e*inv-scaled row bias (f16)
__device__ __half g_colb[HEADS * N_POS * HW];   // log2e*inv-scaled col bias (f16)
__device__ float g_y[HEADS * 64 * N_POS];       // per-head projected output Y_h

// ---------------- helpers ----------------------------------------------------
__device__ __forceinline__ uint32_t pkh2(float lo, float hi) {
    uint32_t r;
    asm("cvt.rn.f16x2.f32 %0, %1, %2;" : "=r"(r) : "f"(hi), "f"(lo));
    return r;
}
__device__ __forceinline__ uint32_t ex2h2(uint32_t x) {
    uint32_t r; asm("ex2.approx.f16x2 %0, %1;" : "=r"(r) : "r"(x)); return r;
}
__device__ __forceinline__ uint32_t haddu2(uint32_t a, uint32_t b) {
    uint32_t r; asm("add.rn.f16x2 %0, %1, %2;" : "=r"(r) : "r"(a), "r"(b)); return r;
}
// f32-accumulator MMA
__device__ __forceinline__ void mma_f16(
    float& d0, float& d1, float& d2, float& d3,
    uint32_t a0, uint32_t a1, uint32_t a2, uint32_t a3,
    uint32_t b0, uint32_t b1)
{
    asm("mma.sync.aligned.m16n8k16.row.col.f32.f16.f16.f32 "
        "{%0,%1,%2,%3}, {%4,%5,%6,%7}, {%8,%9}, {%0,%1,%2,%3};"
        : "+f"(d0), "+f"(d1), "+f"(d2), "+f"(d3)
        : "r"(a0), "r"(a1), "r"(a2), "r"(a3), "r"(b0), "r"(b1));
}
// f16-accumulator MMA (S phase)
__device__ __forceinline__ void mma_f16acc(
    uint32_t& d0, uint32_t& d1,
    uint32_t a0, uint32_t a1, uint32_t a2, uint32_t a3,
    uint32_t b0, uint32_t b1)
{
    asm("mma.sync.aligned.m16n8k16.row.col.f16.f16.f16.f16 "
        "{%0,%1}, {%2,%3,%4,%5}, {%6,%7}, {%0,%1};"
        : "+r"(d0), "+r"(d1)
        : "r"(a0), "r"(a1), "r"(a2), "r"(a3), "r"(b0), "r"(b1));
}

#define CP_ASYNC16(dst_smem, src) \
    asm volatile("cp.async.cg.shared.global [%0], [%1], 16;" \
                 :: "r"((unsigned)(dst_smem)), "l"(src))
#define CP_COMMIT()  asm volatile("cp.async.commit_group;")
#define CP_WAIT0()   asm volatile("cp.async.wait_group 0;" ::: "memory")

// ---------------- Kernel 1: QKV projection via HMMA (x split hi/lo) ---------
// Grid (49, 12): by -> mat (q/k/v) x 64-row chunk. 128 threads = 4 warps.
// A = W rows [64 d][32 w] f16x2 (stride 36 words), B = X^T [64 p][32 w].
__global__ __launch_bounds__(128) void qkv_kernel(
    const float* __restrict__ x,
    const float* __restrict__ Wq, const float* __restrict__ bq,
    const float* __restrict__ Wk, const float* __restrict__ bk,
    const float* __restrict__ Wv, const float* __restrict__ bv)
{
    __shared__ uint32_t Ws[64 * 36];
    __shared__ uint32_t Xh[64 * 36];
    __shared__ uint32_t Xl[64 * 36];

    const int p0  = blockIdx.x * 64;
    const int by  = blockIdx.y;
    const int mat = by >> 2;
    const int dl0 = (by & 3) * 64;
    const float* W    = (mat == 0) ? Wq : (mat == 1) ? Wk : Wv;
    const float* bias = (mat == 0) ? bq : (mat == 1) ? bk : bv;

    const int tid = threadIdx.x;
    const int w   = tid >> 5;
    const int ln  = tid & 31;
    const int g   = ln >> 2;
    const int t   = ln & 3;
    const int wd0 = w * 16;

    // stage W chunk as f16x2
    for (int i = tid; i < 2048; i += 128) {
        int r = i >> 5, cw = i & 31;
        float lo = W[(dl0 + r) * 64 + 2 * cw];
        float hi = W[(dl0 + r) * 64 + 2 * cw + 1];
        Ws[r * 36 + cw] = pkh2(lo, hi);
    }
    // stage X^T split hi/lo
    for (int i = tid; i < 2048; i += 128) {
        int p = i & 63, cw = i >> 6;
        for (int c2 = cw; c2 < 32; c2 += 16) {
            float a = x[(2 * c2)     * N_POS + p0 + p];
            float b = x[(2 * c2 + 1) * N_POS + p0 + p];
            __half ah = __float2half(a), bh = __float2half(b);
            float al = a - __half2float(ah), bl = b - __half2float(bh);
            Xh[p * 36 + c2] = pkh2(__half2float(ah), __half2float(bh));
            Xl[p * 36 + c2] = pkh2(al, bl);
        }
        break;   // inner loop covers all c2 for this (p, cw base)
    }
    // the break-pattern above is wrong for coverage; do a clean second pass
    __syncthreads();
    // (clean re-stage to guarantee full coverage)
    for (int i = tid; i < 2048; i += 128) {
        int p = i & 63, c2 = (i >> 6) + ((i >= 2048) ? 0 : 0);
        int cw = i >> 6;               // 0..31
        float a = x[(2 * cw)     * N_POS + p0 + p];
        float b = x[(2 * cw + 1) * N_POS + p0 + p];
        __half ah = __float2half(a), bh = __float2half(b);
        float al = a - __half2float(ah), bl = b - __half2float(bh);
        Xh[p * 36 + cw] = pkh2(__half2float(ah), __half2float(bh));
        Xl[p * 36 + cw] = pkh2(al, bl);
        (void)c2;
    }
    __syncthreads();

    // A fragments
    uint32_t wa[4][4];
#pragma unroll
    for (int kc = 0; kc < 4; kc++) {
        wa[kc][0] = Ws[(wd0 + g)     * 36 + 8 * kc + t];
        wa[kc][1] = Ws[(wd0 + g + 8) * 36 + 8 * kc + t];
        wa[kc][2] = Ws[(wd0 + g)     * 36 + 8 * kc + t + 4];
        wa[kc][3] = Ws[(wd0 + g + 8) * 36 + 8 * kc + t + 4];
    }

    const int dA = dl0 + wd0 + g, dB = dA + 8;
    const float bvA = bias[dA], bvB = bias[dB];
    const int hA = dA & 7, mA = dA >> 3;
    const int hB = dB & 7, mB = dB >> 3;

#pragma unroll
    for (int nt = 0; nt < 8; nt++) {
        const uint32_t* xhr = &Xh[(8 * nt + g) * 36 + t];
        const uint32_t* xlr = &Xl[(8 * nt + g) * 36 + t];
        float y0 = 0.f, y1 = 0.f, y2 = 0.f, y3 = 0.f;
#pragma unroll
        for (int kc = 0; kc < 4; kc++) {
            mma_f16(y0, y1, y2, y3, wa[kc][0], wa[kc][1], wa[kc][2], wa[kc][3],
                    xhr[8 * kc], xhr[8 * kc + 4]);
            mma_f16(y0, y1, y2, y3, wa[kc][0], wa[kc][1], wa[kc][2], wa[kc][3],
                    xlr[8 * kc], xlr[8 * kc + 4]);
        }
        y0 += bvA; y1 += bvA; y2 += bvB; y3 += bvB;
        const int p = p0 + 8 * nt + 2 * t;
        if (mat == 0) {
            g_q[(hA * N_POS + p)     * MIDC + mA] = y0;
            g_q[(hA * N_POS + p + 1) * MIDC + mA] = y1;
            g_q[(hB * N_POS + p)     * MIDC + mB] = y2;
            g_q[(hB * N_POS + p + 1) * MIDC + mB] = y3;
        } else if (mat == 1) {
            g_k[(hA * N_POS + p)     * MIDC + mA] = __float2half(y0);
            g_k[(hA * N_POS + p + 1) * MIDC + mA] = __float2half(y1);
            g_k[(hB * N_POS + p)     * MIDC + mB] = __float2half(y2);
            g_k[(hB * N_POS + p + 1) * MIDC + mB] = __float2half(y3);
        } else {
            *(__half2*)&g_vT[(hA * MIDC + mA) * N_POS + p] =
                __floats2half2_rn(y0, y1);
            *(__half2*)&g_vT[(hB * MIDC + mB) * N_POS + p] =
                __floats2half2_rn(y2, y3);
        }
    }
}

// ---------------- Kernel 2: bias precompute (x INV*LOG2E, f16 out) ----------
__global__ __launch_bounds__(256) void bias_kernel(
    const float* __restrict__ rowT, const float* __restrict__ colT)
{
    int idx = blockIdx.x * 256 + threadIdx.x;
    int h   = idx / (N_POS * 112);
    int rem = idx - h * (N_POS * 112);
    int p   = rem / 112;
    int t   = rem - p * 112;
    const float* Qp = &g_q[(h * N_POS + p) * MIDC];
    const float sc = INV * LOG2E;

    if (t < HW) {
        int i = p / HW;
        const float4* tr = (const float4*)&rowT[(t - i + 55) * 16];
        const float4* qp = (const float4*)Qp;
        float acc = 0.f;
#pragma unroll
        for (int m = 0; m < 4; m++) {
            float4 a = qp[m], b = tr[m];
            acc += a.x * b.x + a.y * b.y + a.z * b.z + a.w * b.w;
        }
        g_rowb[(h * N_POS + p) * HW + t] = __float2half(acc * sc);
    } else {
        int l = t - HW, j = p % HW;
        const float4* tc = (const float4*)&colT[(l - j + 55) * 16];
        const float4* qp = (const float4*)(Qp + 16);
        float acc = 0.f;
#pragma unroll
        for (int m = 0; m < 4; m++) {
            float4 a = qp[m], b = tc[m];
            acc += a.x * b.x + a.y * b.y + a.z * b.z + a.w * b.w;
        }
        g_colb[(h * N_POS + p) * HW + l] = __float2half(acc * sc);
    }
}

// ---------------- Kernel 3: fp16 flash attention + fused out-projection -----
// (R14-proven, unchanged)
#define KOFF0 0
#define KOFF1 8960
#define VOFF0 17920
#define VOFF1 26624
#define PMOFF 35328
#define WOSOFF 35328
#define OSOFF  40448
#define SMEMB 52736

__global__ __launch_bounds__(128, 3) void attn_kernel(
    const float* __restrict__ Wo)
{
    extern __shared__ char smc[];

    const int bx  = blockIdx.x;
    const int h   = bx / 49;
    const int qt  = bx - h * 49;
    const int p0  = qt * 64;

    const int tid = threadIdx.x;
    const int w   = tid >> 5;
    const int ln  = tid & 31;
    const int g   = ln >> 2;
    const int t   = ln & 3;
    const int wq0 = w * 16;
    const int hbase = h * N_POS;

    const unsigned sm_u32 = (unsigned)__cvta_generic_to_shared(smc);

    uint32_t qa[2][4];
    {
        const float sc = INV * LOG2E;
        const float* Q0 = &g_q[(hbase + p0 + wq0 + g) * MIDC];
        const float* Q8 = Q0 + 8 * MIDC;
#pragma unroll
        for (int kc = 0; kc < 2; kc++) {
            int c0 = 16 * kc + 2 * t;
            qa[kc][0] = pkh2(Q0[c0]     * sc, Q0[c0 + 1] * sc);
            qa[kc][1] = pkh2(Q8[c0]     * sc, Q8[c0 + 1] * sc);
            qa[kc][2] = pkh2(Q0[c0 + 8] * sc, Q0[c0 + 9] * sc);
            qa[kc][3] = pkh2(Q8[c0 + 8] * sc, Q8[c0 + 9] * sc);
        }
    }

    uint32_t cb2g[7], cb2g8[7];
    {
        const __half* C0 = &g_colb[(hbase + p0 + wq0 + g) * HW];
        const __half* C8 = C0 + 8 * HW;
#pragma unroll
        for (int nt = 0; nt < 7; nt++) {
            int c0 = 8 * nt + 2 * t;
            cb2g[nt]  = *(const uint32_t*)(C0 + c0);
            cb2g8[nt] = *(const uint32_t*)(C8 + c0);
        }
    }

    const __half* rbg  = g_rowb + (hbase + p0 + wq0 + g) * HW;
    const __half* rbg8 = rbg + 8 * HW;
    uint32_t rbnx0 = *(const uint32_t*)(rbg);
    uint32_t rbnx8 = *(const uint32_t*)(rbg8);

    float Oa[4][4];
#pragma unroll
    for (int mt = 0; mt < 4; mt++)
#pragma unroll
        for (int j = 0; j < 4; j++) Oa[mt][j] = 0.f;
    float lsum0 = 0.f, lsum1 = 0.f;

    auto load_tile = [&](int c, int buf) {
        const uint32_t kof = sm_u32 + (buf ? KOFF1 : KOFF0);
        const uint32_t vof = sm_u32 + (buf ? VOFF1 : VOFF0);
        const __half* Kg = g_k  + (hbase + c * 112) * MIDC;
        const __half* Vg = g_vT + h * MIDC * N_POS + c * 112;
#pragma unroll 7
        for (int i = tid; i < 896; i += 128) {
            if (i < 448) {
                int r = i >> 2, cc = i & 3;
                CP_ASYNC16(kof + r * 80 + cc * 16, Kg + r * 32 + cc * 8);
            } else {
                int j = i - 448;
                int m = j / 14, t14 = j - m * 14;
                CP_ASYNC16(vof + m * 272 + t14 * 16, Vg + m * N_POS + t14 * 8);
            }
        }
        CP_COMMIT();
    };

    load_tile(0, 0);

    for (int c = 0; c < NCH; c++) {
        const int buf = c & 1;
        CP_WAIT0();
        __syncthreads();
        if (c + 1 < NCH) load_tile(c + 1, (c + 1) & 1);

        const uint32_t* Ku = (const uint32_t*)(smc + (buf ? KOFF1 : KOFF0));
        const uint32_t* Vw = (const uint32_t*)(smc + (buf ? VOFF1 : VOFF0));
        uint32_t* Pw = (uint32_t*)(smc + PMOFF);

        uint32_t rbc0 = rbnx0, rbc8 = rbnx8;
        if (c + 1 < NCH) {
            rbnx0 = *(const uint32_t*)(rbg  + 2 * (c + 1));
            rbnx8 = *(const uint32_t*)(rbg8 + 2 * (c + 1));
        }
        uint32_t r2[2][2];
        {
            __half2 a = *(__half2*)&rbc0, b = *(__half2*)&rbc8;
            __half2 t00 = __half2half2(__low2half(a)),  t10 = __half2half2(__high2half(a));
            __half2 t01 = __half2half2(__low2half(b)),  t11 = __half2half2(__high2half(b));
            r2[0][0] = *(uint32_t*)&t00; r2[1][0] = *(uint32_t*)&t10;
            r2[0][1] = *(uint32_t*)&t01; r2[1][1] = *(uint32_t*)&t11;
        }

        uint32_t ls2g = 0u, ls2g8 = 0u;

#pragma unroll
        for (int nt = 0; nt < 14; nt++) {
            const int sel = (nt < 7) ? 0 : 1;
            const int ci  = (nt < 7) ? nt : nt - 7;
            const uint32_t* krow = Ku + (8 * nt + g) * 20 + t;
            uint32_t b00 = krow[0], b01 = krow[4], b10 = krow[8], b11 = krow[12];
            uint32_t d0 = haddu2(r2[sel][0], cb2g[ci]);
            uint32_t d1 = haddu2(r2[sel][1], cb2g8[ci]);
            mma_f16acc(d0, d1, qa[0][0], qa[0][1], qa[0][2], qa[0][3], b00, b01);
            mma_f16acc(d0, d1, qa[1][0], qa[1][1], qa[1][2], qa[1][3], b10, b11);
            uint32_t e0 = ex2h2(d0);
            uint32_t e1 = ex2h2(d1);
            ls2g  = haddu2(ls2g,  e0);
            ls2g8 = haddu2(ls2g8, e1);
            Pw[(wq0 + g)     * 68 + 4 * nt + t] = e0;
            Pw[(wq0 + g + 8) * 68 + 4 * nt + t] = e1;
        }
        {
            __half2 a = *(__half2*)&ls2g, b = *(__half2*)&ls2g8;
            lsum0 += __low2float(a) + __high2float(a);
            lsum1 += __low2float(b) + __high2float(b);
        }

        __syncwarp();

#pragma unroll
        for (int kc = 0; kc < 7; kc++) {
            const uint32_t* pr0 = Pw + (wq0 + g)     * 68 + 8 * kc + t;
            const uint32_t* pr8 = Pw + (wq0 + g + 8) * 68 + 8 * kc + t;
            uint32_t a0 = pr0[0], a1 = pr8[0], a2 = pr0[4], a3 = pr8[4];
#pragma unroll
            for (int mt = 0; mt < 4; mt++) {
                const uint32_t* vrow = Vw + (8 * mt + g) * 68 + 8 * kc + t;
                mma_f16(Oa[mt][0], Oa[mt][1], Oa[mt][2], Oa[mt][3],
                        a0, a1, a2, a3, vrow[0], vrow[4]);
            }
        }
    }

    lsum0 += __shfl_xor_sync(0xffffffffu, lsum0, 1);
    lsum0 += __shfl_xor_sync(0xffffffffu, lsum0, 2);
    lsum1 += __shfl_xor_sync(0xffffffffu, lsum1, 1);
    lsum1 += __shfl_xor_sync(0xffffffffu, lsum1, 2);
    const float rinv0 = 1.0f / lsum0;
    const float rinv1 = 1.0f / lsum1;

    __syncthreads();

    {
        uint32_t* Os = (uint32_t*)(smc + OSOFF);
#pragma unroll
        for (int mt = 0; mt < 4; mt++) {
            uint32_t lo = pkh2(Oa[mt][0] * rinv0, Oa[mt][1] * rinv0);
            uint32_t hi = pkh2(Oa[mt][2] * rinv1, Oa[mt][3] * rinv1);
            Os[(wq0 + g)     * 20 + 4 * mt + t] = lo;
            Os[(wq0 + g + 8) * 20 + 4 * mt + t] = hi;
        }
    }
    {
        __half* Wos = (__half*)(smc + WOSOFF);
        for (int i = tid; i < 2048; i += 128) {
            int co = i >> 5, m = i & 31;
            Wos[co * 40 + m] = __float2half(Wo[co * 256 + m * 8 + h]);
        }
    }
    __syncthreads();

    {
        const int wco = w * 16;
        const uint32_t* Ww = (const uint32_t*)(smc + WOSOFF);
        const uint32_t* Os = (const uint32_t*)(smc + OSOFF);
        uint32_t wa[2][4];
#pragma unroll
        for (int kc = 0; kc < 2; kc++) {
            wa[kc][0] = Ww[(wco + g)     * 20 + 8 * kc + t];
            wa[kc][1] = Ww[(wco + g + 8) * 20 + 8 * kc + t];
            wa[kc][2] = Ww[(wco + g)     * 20 + 8 * kc + t + 4];
            wa[kc][3] = Ww[(wco + g + 8) * 20 + 8 * kc + t + 4];
        }
#pragma unroll
        for (int nt = 0; nt < 8; nt++) {
            const uint32_t* orow = Os + (8 * nt + g) * 20 + t;
            uint32_t b00 = orow[0], b01 = orow[4], b10 = orow[8], b11 = orow[12];
            float y0 = 0.f, y1 = 0.f, y2 = 0.f, y3 = 0.f;
            mma_f16(y0, y1, y2, y3, wa[0][0], wa[0][1], wa[0][2], wa[0][3], b00, b01);
            mma_f16(y0, y1, y2, y3, wa[1][0], wa[1][1], wa[1][2], wa[1][3], b10, b11);
            int co = wco + g;
            int pp = p0 + 8 * nt + 2 * t;
            *(float2*)&g_y[(h * 64 + co)     * N_POS + pp] = make_float2(y0, y1);
            *(float2*)&g_y[(h * 64 + co + 8) * N_POS + pp] = make_float2(y2, y3);
        }
    }
}

// ---------------- Kernel 4: sum heads + bias --------------------------------
// 392 blocks x 128 threads; one float4 of output per thread.
__global__ __launch_bounds__(128) void sum_kernel(
    const float* __restrict__ bo, float* __restrict__ out)
{
    int idx = blockIdx.x * 128 + threadIdx.x;   // 0..50175
    int co  = idx / 784;
    int pw  = idx - co * 784;
    int p4  = pw * 4;
    float b = bo[co];
    float4 s = make_float4(b, b, b, b);
#pragma unroll
    for (int h = 0; h < HEADS; h++) {
        float4 v = *(const float4*)&g_y[(h * 64 + co) * N_POS + p4];
        s.x += v.x; s.y += v.y; s.z += v.z; s.w += v.w;
    }
    *(float4*)&out[co * N_POS + p4] = s;
}

// ---------------- launch -----------------------------------------------------
extern "C" void kernel_launch(void* const* d_in, const int* in_sizes, int n_in,
                              void* d_out, int out_size)
{
    const float* x    = (const float*)d_in[0];
    const float* Wq   = (const float*)d_in[1];
    const float* bq   = (const float*)d_in[2];
    const float* Wk   = (const float*)d_in[3];
    const float* bk   = (const float*)d_in[4];
    const float* Wv   = (const float*)d_in[5];
    const float* bv   = (const float*)d_in[6];
    const float* Wo   = (const float*)d_in[7];
    const float* bo   = (const float*)d_in[8];
    const float* rowT = (const float*)d_in[9];
    const float* colT = (const float*)d_in[10];

    cudaFuncSetAttribute(attn_kernel,
                         cudaFuncAttributeMaxDynamicSharedMemorySize, SMEMB);

    qkv_kernel<<<dim3(49, 12), 128>>>(x, Wq, bq, Wk, bk, Wv, bv);
    bias_kernel<<<10976, 256>>>(rowT, colT);
    attn_kernel<<<392, 128, SMEMB>>>(Wo);
    sum_kernel<<<392, 128>>>(bo, (float*)d_out);
}

// round 16
// speedup vs baseline: 1.6419x; 1.0119x over previous
#include <cuda_runtime.h>
#include <cuda_fp16.h>
#include <math_constants.h>
#include <cstdint>

#define N_POS 3136
#define HW    56
#define MIDC  32
#define HEADS 8
#define INV   0.125f   // 1/sqrt(64)
#define LOG2E 1.4426950408889634f
#define NCH   28       // 28 chunks of 112 keys (full 3136 per block)

// ---------------- scratch (global, no allocation in kernel_launch) ----------
__device__ float  g_q [HEADS * N_POS * MIDC];   // [h][p][m] fp32
__device__ __half g_k [HEADS * N_POS * MIDC];   // [h][p][m] fp16
__device__ __half g_vT[HEADS * MIDC * N_POS];   // [h][m][p] fp16 (transposed V)
__device__ __half g_rowb[HEADS * N_POS * HW];   // log2e*inv-scaled row bias (f16)
__device__ __half g_colb[HEADS * N_POS * HW];   // log2e*inv-scaled col bias (f16)

// ---------------- helpers ----------------------------------------------------
__device__ __forceinline__ uint32_t pkh2(float lo, float hi) {
    uint32_t r;
    asm("cvt.rn.f16x2.f32 %0, %1, %2;" : "=r"(r) : "f"(hi), "f"(lo));
    return r;
}
__device__ __forceinline__ uint32_t ex2h2(uint32_t x) {
    uint32_t r; asm("ex2.approx.f16x2 %0, %1;" : "=r"(r) : "r"(x)); return r;
}
__device__ __forceinline__ uint32_t haddu2(uint32_t a, uint32_t b) {
    uint32_t r; asm("add.rn.f16x2 %0, %1, %2;" : "=r"(r) : "r"(a), "r"(b)); return r;
}
// f32-accumulator MMA
__device__ __forceinline__ void mma_f16(
    float& d0, float& d1, float& d2, float& d3,
    uint32_t a0, uint32_t a1, uint32_t a2, uint32_t a3,
    uint32_t b0, uint32_t b1)
{
    asm("mma.sync.aligned.m16n8k16.row.col.f32.f16.f16.f32 "
        "{%0,%1,%2,%3}, {%4,%5,%6,%7}, {%8,%9}, {%0,%1,%2,%3};"
        : "+f"(d0), "+f"(d1), "+f"(d2), "+f"(d3)
        : "r"(a0), "r"(a1), "r"(a2), "r"(a3), "r"(b0), "r"(b1));
}
// f16-accumulator MMA (S phase)
__device__ __forceinline__ void mma_f16acc(
    uint32_t& d0, uint32_t& d1,
    uint32_t a0, uint32_t a1, uint32_t a2, uint32_t a3,
    uint32_t b0, uint32_t b1)
{
    asm("mma.sync.aligned.m16n8k16.row.col.f16.f16.f16.f16 "
        "{%0,%1}, {%2,%3,%4,%5}, {%6,%7}, {%0,%1};"
        : "+r"(d0), "+r"(d1)
        : "r"(a0), "r"(a1), "r"(a2), "r"(a3), "r"(b0), "r"(b1));
}

#define CP_ASYNC16(dst_smem, src) \
    asm volatile("cp.async.cg.shared.global [%0], [%1], 16;" \
                 :: "r"((unsigned)(dst_smem)), "l"(src))
#define CP_COMMIT()  asm volatile("cp.async.commit_group;")
#define CP_WAIT0()   asm volatile("cp.async.wait_group 0;" ::: "memory")

// ---------------- Kernel 1: QKV projection via HMMA (x split hi/lo) ---------
// Grid (49, 12): by -> mat (q/k/v) x 64-row chunk. 128 threads = 4 warps.
__global__ __launch_bounds__(128) void qkv_kernel(
    const float* __restrict__ x,
    const float* __restrict__ Wq, const float* __restrict__ bq,
    const float* __restrict__ Wk, const float* __restrict__ bk,
    const float* __restrict__ Wv, const float* __restrict__ bv)
{
    __shared__ uint32_t Ws[64 * 36];
    __shared__ uint32_t Xh[64 * 36];
    __shared__ uint32_t Xl[64 * 36];

    const int p0  = blockIdx.x * 64;
    const int by  = blockIdx.y;
    const int mat = by >> 2;
    const int dl0 = (by & 3) * 64;
    const float* W    = (mat == 0) ? Wq : (mat == 1) ? Wk : Wv;
    const float* bias = (mat == 0) ? bq : (mat == 1) ? bk : bv;

    const int tid = threadIdx.x;
    const int w   = tid >> 5;
    const int ln  = tid & 31;
    const int g   = ln >> 2;
    const int t   = ln & 3;
    const int wd0 = w * 16;

    // stage W chunk as f16x2
    for (int i = tid; i < 2048; i += 128) {
        int r = i >> 5, cw = i & 31;
        float lo = W[(dl0 + r) * 64 + 2 * cw];
        float hi = W[(dl0 + r) * 64 + 2 * cw + 1];
        Ws[r * 36 + cw] = pkh2(lo, hi);
    }
    // stage X^T split hi/lo (single clean pass: i -> (p, cw))
    for (int i = tid; i < 2048; i += 128) {
        int p = i & 63, cw = i >> 6;
        float a = x[(2 * cw)     * N_POS + p0 + p];
        float b = x[(2 * cw + 1) * N_POS + p0 + p];
        __half ah = __float2half(a), bh = __float2half(b);
        float al = a - __half2float(ah), bl = b - __half2float(bh);
        Xh[p * 36 + cw] = pkh2(__half2float(ah), __half2float(bh));
        Xl[p * 36 + cw] = pkh2(al, bl);
    }
    __syncthreads();

    // A fragments
    uint32_t wa[4][4];
#pragma unroll
    for (int kc = 0; kc < 4; kc++) {
        wa[kc][0] = Ws[(wd0 + g)     * 36 + 8 * kc + t];
        wa[kc][1] = Ws[(wd0 + g + 8) * 36 + 8 * kc + t];
        wa[kc][2] = Ws[(wd0 + g)     * 36 + 8 * kc + t + 4];
        wa[kc][3] = Ws[(wd0 + g + 8) * 36 + 8 * kc + t + 4];
    }

    const int dA = dl0 + wd0 + g, dB = dA + 8;
    const float bvA = bias[dA], bvB = bias[dB];
    const int hA = dA & 7, mA = dA >> 3;
    const int hB = dB & 7, mB = dB >> 3;

#pragma unroll
    for (int nt = 0; nt < 8; nt++) {
        const uint32_t* xhr = &Xh[(8 * nt + g) * 36 + t];
        const uint32_t* xlr = &Xl[(8 * nt + g) * 36 + t];
        float y0 = 0.f, y1 = 0.f, y2 = 0.f, y3 = 0.f;
#pragma unroll
        for (int kc = 0; kc < 4; kc++) {
            mma_f16(y0, y1, y2, y3, wa[kc][0], wa[kc][1], wa[kc][2], wa[kc][3],
                    xhr[8 * kc], xhr[8 * kc + 4]);
            mma_f16(y0, y1, y2, y3, wa[kc][0], wa[kc][1], wa[kc][2], wa[kc][3],
                    xlr[8 * kc], xlr[8 * kc + 4]);
        }
        y0 += bvA; y1 += bvA; y2 += bvB; y3 += bvB;
        const int p = p0 + 8 * nt + 2 * t;
        if (mat == 0) {
            g_q[(hA * N_POS + p)     * MIDC + mA] = y0;
            g_q[(hA * N_POS + p + 1) * MIDC + mA] = y1;
            g_q[(hB * N_POS + p)     * MIDC + mB] = y2;
            g_q[(hB * N_POS + p + 1) * MIDC + mB] = y3;
        } else if (mat == 1) {
            g_k[(hA * N_POS + p)     * MIDC + mA] = __float2half(y0);
            g_k[(hA * N_POS + p + 1) * MIDC + mA] = __float2half(y1);
            g_k[(hB * N_POS + p)     * MIDC + mB] = __float2half(y2);
            g_k[(hB * N_POS + p + 1) * MIDC + mB] = __float2half(y3);
        } else {
            *(__half2*)&g_vT[(hA * MIDC + mA) * N_POS + p] =
                __floats2half2_rn(y0, y1);
            *(__half2*)&g_vT[(hB * MIDC + mB) * N_POS + p] =
                __floats2half2_rn(y2, y3);
        }
    }
}

// ---------------- Kernel 2: bias precompute (x INV*LOG2E, f16 out) ----------
__global__ __launch_bounds__(256) void bias_kernel(
    const float* __restrict__ rowT, const float* __restrict__ colT)
{
    int idx = blockIdx.x * 256 + threadIdx.x;
    int h   = idx / (N_POS * 112);
    int rem = idx - h * (N_POS * 112);
    int p   = rem / 112;
    int t   = rem - p * 112;
    const float* Qp = &g_q[(h * N_POS + p) * MIDC];
    const float sc = INV * LOG2E;

    if (t < HW) {
        int i = p / HW;
        const float4* tr = (const float4*)&rowT[(t - i + 55) * 16];
        const float4* qp = (const float4*)Qp;
        float acc = 0.f;
#pragma unroll
        for (int m = 0; m < 4; m++) {
            float4 a = qp[m], b = tr[m];
            acc += a.x * b.x + a.y * b.y + a.z * b.z + a.w * b.w;
        }
        g_rowb[(h * N_POS + p) * HW + t] = __float2half(acc * sc);
    } else {
        int l = t - HW, j = p % HW;
        const float4* tc = (const float4*)&colT[(l - j + 55) * 16];
        const float4* qp = (const float4*)(Qp + 16);
        float acc = 0.f;
#pragma unroll
        for (int m = 0; m < 4; m++) {
            float4 a = qp[m], b = tc[m];
            acc += a.x * b.x + a.y * b.y + a.z * b.z + a.w * b.w;
        }
        g_colb[(h * N_POS + p) * HW + l] = __float2half(acc * sc);
    }
}

// ---------------- Kernel 3: init output with bias ---------------------------
__global__ __launch_bounds__(128) void init_kernel(
    const float* __restrict__ bo, float* __restrict__ out)
{
    int idx = blockIdx.x * 128 + threadIdx.x;   // 0..50175, one float4 each
    int co  = idx / 784;
    int p4  = (idx - co * 784) * 4;
    float b = bo[co];
    *(float4*)&out[co * N_POS + p4] = make_float4(b, b, b, b);
}

// ---------------- Kernel 4: fp16 flash attention + fused out-projection -----
// 392 blocks = 8 heads x 49 q-tiles; mainloop identical to R14/R15-proven.
// Epilogue: Y_h = Wo_h @ (O/L) via HMMA, atomically accumulated into out.
#define KOFF0 0
#define KOFF1 8960
#define VOFF0 17920
#define VOFF1 26624
#define PMOFF 35328
#define WOSOFF 35328
#define OSOFF  40448
#define SMEMB 52736

__global__ __launch_bounds__(128, 3) void attn_kernel(
    const float* __restrict__ Wo, float* __restrict__ out)
{
    extern __shared__ char smc[];

    const int bx  = blockIdx.x;
    const int h   = bx / 49;
    const int qt  = bx - h * 49;
    const int p0  = qt * 64;

    const int tid = threadIdx.x;
    const int w   = tid >> 5;
    const int ln  = tid & 31;
    const int g   = ln >> 2;
    const int t   = ln & 3;
    const int wq0 = w * 16;
    const int hbase = h * N_POS;

    const unsigned sm_u32 = (unsigned)__cvta_generic_to_shared(smc);

    uint32_t qa[2][4];
    {
        const float sc = INV * LOG2E;
        const float* Q0 = &g_q[(hbase + p0 + wq0 + g) * MIDC];
        const float* Q8 = Q0 + 8 * MIDC;
#pragma unroll
        for (int kc = 0; kc < 2; kc++) {
            int c0 = 16 * kc + 2 * t;
            qa[kc][0] = pkh2(Q0[c0]     * sc, Q0[c0 + 1] * sc);
            qa[kc][1] = pkh2(Q8[c0]     * sc, Q8[c0 + 1] * sc);
            qa[kc][2] = pkh2(Q0[c0 + 8] * sc, Q0[c0 + 9] * sc);
            qa[kc][3] = pkh2(Q8[c0 + 8] * sc, Q8[c0 + 9] * sc);
        }
    }

    uint32_t cb2g[7], cb2g8[7];
    {
        const __half* C0 = &g_colb[(hbase + p0 + wq0 + g) * HW];
        const __half* C8 = C0 + 8 * HW;
#pragma unroll
        for (int nt = 0; nt < 7; nt++) {
            int c0 = 8 * nt + 2 * t;
            cb2g[nt]  = *(const uint32_t*)(C0 + c0);
            cb2g8[nt] = *(const uint32_t*)(C8 + c0);
        }
    }

    const __half* rbg  = g_rowb + (hbase + p0 + wq0 + g) * HW;
    const __half* rbg8 = rbg + 8 * HW;
    uint32_t rbnx0 = *(const uint32_t*)(rbg);
    uint32_t rbnx8 = *(const uint32_t*)(rbg8);

    float Oa[4][4];
#pragma unroll
    for (int mt = 0; mt < 4; mt++)
#pragma unroll
        for (int j = 0; j < 4; j++) Oa[mt][j] = 0.f;
    float lsum0 = 0.f, lsum1 = 0.f;

    auto load_tile = [&](int c, int buf) {
        const uint32_t kof = sm_u32 + (buf ? KOFF1 : KOFF0);
        const uint32_t vof = sm_u32 + (buf ? VOFF1 : VOFF0);
        const __half* Kg = g_k  + (hbase + c * 112) * MIDC;
        const __half* Vg = g_vT + h * MIDC * N_POS + c * 112;
#pragma unroll 7
        for (int i = tid; i < 896; i += 128) {
            if (i < 448) {
                int r = i >> 2, cc = i & 3;
                CP_ASYNC16(kof + r * 80 + cc * 16, Kg + r * 32 + cc * 8);
            } else {
                int j = i - 448;
                int m = j / 14, t14 = j - m * 14;
                CP_ASYNC16(vof + m * 272 + t14 * 16, Vg + m * N_POS + t14 * 8);
            }
        }
        CP_COMMIT();
    };

    load_tile(0, 0);

    for (int c = 0; c < NCH; c++) {
        const int buf = c & 1;
        CP_WAIT0();
        __syncthreads();
        if (c + 1 < NCH) load_tile(c + 1, (c + 1) & 1);

        const uint32_t* Ku = (const uint32_t*)(smc + (buf ? KOFF1 : KOFF0));
        const uint32_t* Vw = (const uint32_t*)(smc + (buf ? VOFF1 : VOFF0));
        uint32_t* Pw = (uint32_t*)(smc + PMOFF);

        uint32_t rbc0 = rbnx0, rbc8 = rbnx8;
        if (c + 1 < NCH) {
            rbnx0 = *(const uint32_t*)(rbg  + 2 * (c + 1));
            rbnx8 = *(const uint32_t*)(rbg8 + 2 * (c + 1));
        }
        uint32_t r2[2][2];
        {
            __half2 a = *(__half2*)&rbc0, b = *(__half2*)&rbc8;
            __half2 t00 = __half2half2(__low2half(a)),  t10 = __half2half2(__high2half(a));
            __half2 t01 = __half2half2(__low2half(b)),  t11 = __half2half2(__high2half(b));
            r2[0][0] = *(uint32_t*)&t00; r2[1][0] = *(uint32_t*)&t10;
            r2[0][1] = *(uint32_t*)&t01; r2[1][1] = *(uint32_t*)&t11;
        }

        uint32_t ls2g = 0u, ls2g8 = 0u;

#pragma unroll
        for (int nt = 0; nt < 14; nt++) {
            const int sel = (nt < 7) ? 0 : 1;
            const int ci  = (nt < 7) ? nt : nt - 7;
            const uint32_t* krow = Ku + (8 * nt + g) * 20 + t;
            uint32_t b00 = krow[0], b01 = krow[4], b10 = krow[8], b11 = krow[12];
            uint32_t d0 = haddu2(r2[sel][0], cb2g[ci]);
            uint32_t d1 = haddu2(r2[sel][1], cb2g8[ci]);
            mma_f16acc(d0, d1, qa[0][0], qa[0][1], qa[0][2], qa[0][3], b00, b01);
            mma_f16acc(d0, d1, qa[1][0], qa[1][1], qa[1][2], qa[1][3], b10, b11);
            uint32_t e0 = ex2h2(d0);
            uint32_t e1 = ex2h2(d1);
            ls2g  = haddu2(ls2g,  e0);
            ls2g8 = haddu2(ls2g8, e1);
            Pw[(wq0 + g)     * 68 + 4 * nt + t] = e0;
            Pw[(wq0 + g + 8) * 68 + 4 * nt + t] = e1;
        }
        {
            __half2 a = *(__half2*)&ls2g, b = *(__half2*)&ls2g8;
            lsum0 += __low2float(a) + __high2float(a);
            lsum1 += __low2float(b) + __high2float(b);
        }

        __syncwarp();

#pragma unroll
        for (int kc = 0; kc < 7; kc++) {
            const uint32_t* pr0 = Pw + (wq0 + g)     * 68 + 8 * kc + t;
            const uint32_t* pr8 = Pw + (wq0 + g + 8) * 68 + 8 * kc + t;
            uint32_t a0 = pr0[0], a1 = pr8[0], a2 = pr0[4], a3 = pr8[4];
#pragma unroll
            for (int mt = 0; mt < 4; mt++) {
                const uint32_t* vrow = Vw + (8 * mt + g) * 68 + 8 * kc + t;
                mma_f16(Oa[mt][0], Oa[mt][1], Oa[mt][2], Oa[mt][3],
                        a0, a1, a2, a3, vrow[0], vrow[4]);
            }
        }
    }

    lsum0 += __shfl_xor_sync(0xffffffffu, lsum0, 1);
    lsum0 += __shfl_xor_sync(0xffffffffu, lsum0, 2);
    lsum1 += __shfl_xor_sync(0xffffffffu, lsum1, 1);
    lsum1 += __shfl_xor_sync(0xffffffffu, lsum1, 2);
    const float rinv0 = 1.0f / lsum0;
    const float rinv1 = 1.0f / lsum1;

    __syncthreads();

    {
        uint32_t* Os = (uint32_t*)(smc + OSOFF);
#pragma unroll
        for (int mt = 0; mt < 4; mt++) {
            uint32_t lo = pkh2(Oa[mt][0] * rinv0, Oa[mt][1] * rinv0);
            uint32_t hi = pkh2(Oa[mt][2] * rinv1, Oa[mt][3] * rinv1);
            Os[(wq0 + g)     * 20 + 4 * mt + t] = lo;
            Os[(wq0 + g + 8) * 20 + 4 * mt + t] = hi;
        }
    }
    {
        __half* Wos = (__half*)(smc + WOSOFF);
        for (int i = tid; i < 2048; i += 128) {
            int co = i >> 5, m = i & 31;
            Wos[co * 40 + m] = __float2half(Wo[co * 256 + m * 8 + h]);
        }
    }
    __syncthreads();

    {
        const int wco = w * 16;
        const uint32_t* Ww = (const uint32_t*)(smc + WOSOFF);
        const uint32_t* Os = (const uint32_t*)(smc + OSOFF);
        uint32_t wa[2][4];
#pragma unroll
        for (int kc = 0; kc < 2; kc++) {
            wa[kc][0] = Ww[(wco + g)     * 20 + 8 * kc + t];
            wa[kc][1] = Ww[(wco + g + 8) * 20 + 8 * kc + t];
            wa[kc][2] = Ww[(wco + g)     * 20 + 8 * kc + t + 4];
            wa[kc][3] = Ww[(wco + g + 8) * 20 + 8 * kc + t + 4];
        }
#pragma unroll
        for (int nt = 0; nt < 8; nt++) {
            const uint32_t* orow = Os + (8 * nt + g) * 20 + t;
            uint32_t b00 = orow[0], b01 = orow[4], b10 = orow[8], b11 = orow[12];
            float y0 = 0.f, y1 = 0.f, y2 = 0.f, y3 = 0.f;
            mma_f16(y0, y1, y2, y3, wa[0][0], wa[0][1], wa[0][2], wa[0][3], b00, b01);
            mma_f16(y0, y1, y2, y3, wa[1][0], wa[1][1], wa[1][2], wa[1][3], b10, b11);
            int co = wco + g;
            int pp = p0 + 8 * nt + 2 * t;
            atomicAdd(&out[co       * N_POS + pp],     y0);
            atomicAdd(&out[co       * N_POS + pp + 1], y1);
            atomicAdd(&out[(co + 8) * N_POS + pp],     y2);
            atomicAdd(&out[(co + 8) * N_POS + pp + 1], y3);
        }
    }
}

// ---------------- launch -----------------------------------------------------
extern "C" void kernel_launch(void* const* d_in, const int* in_sizes, int n_in,
                              void* d_out, int out_size)
{
    const float* x    = (const float*)d_in[0];
    const float* Wq   = (const float*)d_in[1];
    const float* bq   = (const float*)d_in[2];
    const float* Wk   = (const float*)d_in[3];
    const float* bk   = (const float*)d_in[4];
    const float* Wv   = (const float*)d_in[5];
    const float* bv   = (const float*)d_in[6];
    const float* Wo   = (const float*)d_in[7];
    const float* bo   = (const float*)d_in[8];
    const float* rowT = (const float*)d_in[9];
    const float* colT = (const float*)d_in[10];

    cudaFuncSetAttribute(attn_kernel,
                         cudaFuncAttributeMaxDynamicSharedMemorySize, SMEMB);

    qkv_kernel<<<dim3(49, 12), 128>>>(x, Wq, bq, Wk, bk, Wv, bv);
    bias_kernel<<<10976, 256>>>(rowT, colT);
    init_kernel<<<392, 128>>>(bo, (float*)d_out);
    attn_kernel<<<392, 128, SMEMB>>>(Wo, (float*)d_out);
}

// round 17
// speedup vs baseline: 1.8629x; 1.1346x over previous
#include <cuda_runtime.h>
#include <cuda_fp16.h>
#include <math_constants.h>
#include <cstdint>

#define N_POS 3136
#define HW    56
#define MIDC  32
#define HEADS 8
#define INV   0.125f   // 1/sqrt(64)
#define LOG2E 1.4426950408889634f
#define NCH   28       // 28 chunks of 112 keys (full 3136 per block)

// ---------------- scratch (global, no allocation in kernel_launch) ----------
__device__ float  g_q [HEADS * N_POS * MIDC];   // [h][p][m] fp32
__device__ __half g_k [HEADS * N_POS * MIDC];   // [h][p][m] fp16
__device__ __half g_vT[HEADS * MIDC * N_POS];   // [h][m][p] fp16 (transposed V)
__device__ __half g_rowb[HEADS * N_POS * HW];   // log2e*inv-scaled row bias (f16)
__device__ __half g_colb[HEADS * N_POS * HW];   // log2e*inv-scaled col bias (f16)

// ---------------- helpers ----------------------------------------------------
__device__ __forceinline__ uint32_t pkh2(float lo, float hi) {
    uint32_t r;
    asm("cvt.rn.f16x2.f32 %0, %1, %2;" : "=r"(r) : "f"(hi), "f"(lo));
    return r;
}
__device__ __forceinline__ uint32_t ex2h2(uint32_t x) {
    uint32_t r; asm("ex2.approx.f16x2 %0, %1;" : "=r"(r) : "r"(x)); return r;
}
__device__ __forceinline__ uint32_t haddu2(uint32_t a, uint32_t b) {
    uint32_t r; asm("add.rn.f16x2 %0, %1, %2;" : "=r"(r) : "r"(a), "r"(b)); return r;
}
// f32-accumulator MMA
__device__ __forceinline__ void mma_f16(
    float& d0, float& d1, float& d2, float& d3,
    uint32_t a0, uint32_t a1, uint32_t a2, uint32_t a3,
    uint32_t b0, uint32_t b1)
{
    asm("mma.sync.aligned.m16n8k16.row.col.f32.f16.f16.f32 "
        "{%0,%1,%2,%3}, {%4,%5,%6,%7}, {%8,%9}, {%0,%1,%2,%3};"
        : "+f"(d0), "+f"(d1), "+f"(d2), "+f"(d3)
        : "r"(a0), "r"(a1), "r"(a2), "r"(a3), "r"(b0), "r"(b1));
}
// f16-accumulator MMA (S phase)
__device__ __forceinline__ void mma_f16acc(
    uint32_t& d0, uint32_t& d1,
    uint32_t a0, uint32_t a1, uint32_t a2, uint32_t a3,
    uint32_t b0, uint32_t b1)
{
    asm("mma.sync.aligned.m16n8k16.row.col.f16.f16.f16.f16 "
        "{%0,%1}, {%2,%3,%4,%5}, {%6,%7}, {%0,%1};"
        : "+r"(d0), "+r"(d1)
        : "r"(a0), "r"(a1), "r"(a2), "r"(a3), "r"(b0), "r"(b1));
}

#define CP_ASYNC16(dst_smem, src) \
    asm volatile("cp.async.cg.shared.global [%0], [%1], 16;" \
                 :: "r"((unsigned)(dst_smem)), "l"(src))
#define CP_COMMIT()  asm volatile("cp.async.commit_group;")
#define CP_WAIT0()   asm volatile("cp.async.wait_group 0;" ::: "memory")

// ---------------- Kernel 1: QKV projection via HMMA (x split hi/lo) ---------
__global__ __launch_bounds__(128) void qkv_kernel(
    const float* __restrict__ x,
    const float* __restrict__ Wq, const float* __restrict__ bq,
    const float* __restrict__ Wk, const float* __restrict__ bk,
    const float* __restrict__ Wv, const float* __restrict__ bv)
{
    __shared__ uint32_t Ws[64 * 36];
    __shared__ uint32_t Xh[64 * 36];
    __shared__ uint32_t Xl[64 * 36];

    const int p0  = blockIdx.x * 64;
    const int by  = blockIdx.y;
    const int mat = by >> 2;
    const int dl0 = (by & 3) * 64;
    const float* W    = (mat == 0) ? Wq : (mat == 1) ? Wk : Wv;
    const float* bias = (mat == 0) ? bq : (mat == 1) ? bk : bv;

    const int tid = threadIdx.x;
    const int w   = tid >> 5;
    const int ln  = tid & 31;
    const int g   = ln >> 2;
    const int t   = ln & 3;
    const int wd0 = w * 16;

    for (int i = tid; i < 2048; i += 128) {
        int r = i >> 5, cw = i & 31;
        float lo = W[(dl0 + r) * 64 + 2 * cw];
        float hi = W[(dl0 + r) * 64 + 2 * cw + 1];
        Ws[r * 36 + cw] = pkh2(lo, hi);
    }
    for (int i = tid; i < 2048; i += 128) {
        int p = i & 63, cw = i >> 6;
        float a = x[(2 * cw)     * N_POS + p0 + p];
        float b = x[(2 * cw + 1) * N_POS + p0 + p];
        __half ah = __float2half(a), bh = __float2half(b);
        float al = a - __half2float(ah), bl = b - __half2float(bh);
        Xh[p * 36 + cw] = pkh2(__half2float(ah), __half2float(bh));
        Xl[p * 36 + cw] = pkh2(al, bl);
    }
    __syncthreads();

    uint32_t wa[4][4];
#pragma unroll
    for (int kc = 0; kc < 4; kc++) {
        wa[kc][0] = Ws[(wd0 + g)     * 36 + 8 * kc + t];
        wa[kc][1] = Ws[(wd0 + g + 8) * 36 + 8 * kc + t];
        wa[kc][2] = Ws[(wd0 + g)     * 36 + 8 * kc + t + 4];
        wa[kc][3] = Ws[(wd0 + g + 8) * 36 + 8 * kc + t + 4];
    }

    const int dA = dl0 + wd0 + g, dB = dA + 8;
    const float bvA = bias[dA], bvB = bias[dB];
    const int hA = dA & 7, mA = dA >> 3;
    const int hB = dB & 7, mB = dB >> 3;

#pragma unroll
    for (int nt = 0; nt < 8; nt++) {
        const uint32_t* xhr = &Xh[(8 * nt + g) * 36 + t];
        const uint32_t* xlr = &Xl[(8 * nt + g) * 36 + t];
        float y0 = 0.f, y1 = 0.f, y2 = 0.f, y3 = 0.f;
#pragma unroll
        for (int kc = 0; kc < 4; kc++) {
            mma_f16(y0, y1, y2, y3, wa[kc][0], wa[kc][1], wa[kc][2], wa[kc][3],
                    xhr[8 * kc], xhr[8 * kc + 4]);
            mma_f16(y0, y1, y2, y3, wa[kc][0], wa[kc][1], wa[kc][2], wa[kc][3],
                    xlr[8 * kc], xlr[8 * kc + 4]);
        }
        y0 += bvA; y1 += bvA; y2 += bvB; y3 += bvB;
        const int p = p0 + 8 * nt + 2 * t;
        if (mat == 0) {
            g_q[(hA * N_POS + p)     * MIDC + mA] = y0;
            g_q[(hA * N_POS + p + 1) * MIDC + mA] = y1;
            g_q[(hB * N_POS + p)     * MIDC + mB] = y2;
            g_q[(hB * N_POS + p + 1) * MIDC + mB] = y3;
        } else if (mat == 1) {
            g_k[(hA * N_POS + p)     * MIDC + mA] = __float2half(y0);
            g_k[(hA * N_POS + p + 1) * MIDC + mA] = __float2half(y1);
            g_k[(hB * N_POS + p)     * MIDC + mB] = __float2half(y2);
            g_k[(hB * N_POS + p + 1) * MIDC + mB] = __float2half(y3);
        } else {
            *(__half2*)&g_vT[(hA * MIDC + mA) * N_POS + p] =
                __floats2half2_rn(y0, y1);
            *(__half2*)&g_vT[(hB * MIDC + mB) * N_POS + p] =
                __floats2half2_rn(y2, y3);
        }
    }
}

// ---------------- Kernel 2: bias precompute (x INV*LOG2E, f16 out) ----------
__global__ __launch_bounds__(256) void bias_kernel(
    const float* __restrict__ rowT, const float* __restrict__ colT)
{
    int idx = blockIdx.x * 256 + threadIdx.x;
    int h   = idx / (N_POS * 112);
    int rem = idx - h * (N_POS * 112);
    int p   = rem / 112;
    int t   = rem - p * 112;
    const float* Qp = &g_q[(h * N_POS + p) * MIDC];
    const float sc = INV * LOG2E;

    if (t < HW) {
        int i = p / HW;
        const float4* tr = (const float4*)&rowT[(t - i + 55) * 16];
        const float4* qp = (const float4*)Qp;
        float acc = 0.f;
#pragma unroll
        for (int m = 0; m < 4; m++) {
            float4 a = qp[m], b = tr[m];
            acc += a.x * b.x + a.y * b.y + a.z * b.z + a.w * b.w;
        }
        g_rowb[(h * N_POS + p) * HW + t] = __float2half(acc * sc);
    } else {
        int l = t - HW, j = p % HW;
        const float4* tc = (const float4*)&colT[(l - j + 55) * 16];
        const float4* qp = (const float4*)(Qp + 16);
        float acc = 0.f;
#pragma unroll
        for (int m = 0; m < 4; m++) {
            float4 a = qp[m], b = tc[m];
            acc += a.x * b.x + a.y * b.y + a.z * b.z + a.w * b.w;
        }
        g_colb[(h * N_POS + p) * HW + l] = __float2half(acc * sc);
    }
}

// ---------------- Kernel 3: init output with bias ---------------------------
__global__ __launch_bounds__(128) void init_kernel(
    const float* __restrict__ bo, float* __restrict__ out)
{
    int idx = blockIdx.x * 128 + threadIdx.x;
    int co  = idx / 784;
    int p4  = (idx - co * 784) * 4;
    float b = bo[co];
    *(float4*)&out[co * N_POS + p4] = make_float4(b, b, b, b);
}

// ---------------- Kernel 4: fp16 flash attention, P-in-registers ------------
// 392 blocks = 8 heads x 49 q-tiles; 128 threads = 4 warps.
// FA2 fragment identity: S D-frag (f16 acc) IS the PV A-frag -> no P smem.
// smem (bytes):
//   K0 @0      : [112 keys][40 halves] (80B rows, 20-word stride)
//   K1 @8960
//   V0 @17920  : [32 ch][136 halves]   (272B rows, 68-word stride)
//   V1 @26624  (end 35328)
//   epilogue reuse: Wos @0 (64co x 20w), Os @8960 (64p x 20w)
#define KOFF0 0
#define KOFF1 8960
#define VOFF0 17920
#define VOFF1 26624
#define WOSOFF 0
#define OSOFF  8960
#define SMEMB 35328

__global__ __launch_bounds__(128, 3) void attn_kernel(
    const float* __restrict__ Wo, float* __restrict__ out)
{
    extern __shared__ char smc[];

    const int bx  = blockIdx.x;
    const int h   = bx / 49;
    const int qt  = bx - h * 49;
    const int p0  = qt * 64;

    const int tid = threadIdx.x;
    const int w   = tid >> 5;
    const int ln  = tid & 31;
    const int g   = ln >> 2;
    const int t   = ln & 3;
    const int wq0 = w * 16;
    const int hbase = h * N_POS;

    const unsigned sm_u32 = (unsigned)__cvta_generic_to_shared(smc);

    uint32_t qa[2][4];
    {
        const float sc = INV * LOG2E;
        const float* Q0 = &g_q[(hbase + p0 + wq0 + g) * MIDC];
        const float* Q8 = Q0 + 8 * MIDC;
#pragma unroll
        for (int kc = 0; kc < 2; kc++) {
            int c0 = 16 * kc + 2 * t;
            qa[kc][0] = pkh2(Q0[c0]     * sc, Q0[c0 + 1] * sc);
            qa[kc][1] = pkh2(Q8[c0]     * sc, Q8[c0 + 1] * sc);
            qa[kc][2] = pkh2(Q0[c0 + 8] * sc, Q0[c0 + 9] * sc);
            qa[kc][3] = pkh2(Q8[c0 + 8] * sc, Q8[c0 + 9] * sc);
        }
    }

    uint32_t cb2g[7], cb2g8[7];
    {
        const __half* C0 = &g_colb[(hbase + p0 + wq0 + g) * HW];
        const __half* C8 = C0 + 8 * HW;
#pragma unroll
        for (int nt = 0; nt < 7; nt++) {
            int c0 = 8 * nt + 2 * t;
            cb2g[nt]  = *(const uint32_t*)(C0 + c0);
            cb2g8[nt] = *(const uint32_t*)(C8 + c0);
        }
    }

    const __half* rbg  = g_rowb + (hbase + p0 + wq0 + g) * HW;
    const __half* rbg8 = rbg + 8 * HW;
    uint32_t rbnx0 = *(const uint32_t*)(rbg);
    uint32_t rbnx8 = *(const uint32_t*)(rbg8);

    float Oa[4][4];
#pragma unroll
    for (int mt = 0; mt < 4; mt++)
#pragma unroll
        for (int j = 0; j < 4; j++) Oa[mt][j] = 0.f;
    float lsum0 = 0.f, lsum1 = 0.f;

    auto load_tile = [&](int c, int buf) {
        const uint32_t kof = sm_u32 + (buf ? KOFF1 : KOFF0);
        const uint32_t vof = sm_u32 + (buf ? VOFF1 : VOFF0);
        const __half* Kg = g_k  + (hbase + c * 112) * MIDC;
        const __half* Vg = g_vT + h * MIDC * N_POS + c * 112;
#pragma unroll 7
        for (int i = tid; i < 896; i += 128) {
            if (i < 448) {
                int r = i >> 2, cc = i & 3;
                CP_ASYNC16(kof + r * 80 + cc * 16, Kg + r * 32 + cc * 8);
            } else {
                int j = i - 448;
                int m = j / 14, t14 = j - m * 14;
                CP_ASYNC16(vof + m * 272 + t14 * 16, Vg + m * N_POS + t14 * 8);
            }
        }
        CP_COMMIT();
    };

    load_tile(0, 0);

    for (int c = 0; c < NCH; c++) {
        const int buf = c & 1;
        CP_WAIT0();
        __syncthreads();
        if (c + 1 < NCH) load_tile(c + 1, (c + 1) & 1);

        const uint32_t* Ku = (const uint32_t*)(smc + (buf ? KOFF1 : KOFF0));
        const uint32_t* Vw = (const uint32_t*)(smc + (buf ? VOFF1 : VOFF0));

        uint32_t rbc0 = rbnx0, rbc8 = rbnx8;
        if (c + 1 < NCH) {
            rbnx0 = *(const uint32_t*)(rbg  + 2 * (c + 1));
            rbnx8 = *(const uint32_t*)(rbg8 + 2 * (c + 1));
        }
        uint32_t r2[2][2];
        {
            __half2 a = *(__half2*)&rbc0, b = *(__half2*)&rbc8;
            __half2 t00 = __half2half2(__low2half(a)),  t10 = __half2half2(__high2half(a));
            __half2 t01 = __half2half2(__low2half(b)),  t11 = __half2half2(__high2half(b));
            r2[0][0] = *(uint32_t*)&t00; r2[1][0] = *(uint32_t*)&t10;
            r2[0][1] = *(uint32_t*)&t01; r2[1][1] = *(uint32_t*)&t11;
        }

        uint32_t ls2g = 0u, ls2g8 = 0u;
        uint32_t pe0[14], pe1[14];      // P fragments in registers (f16x2)

        // ---- S = Q K^T (f16 acc, bias as C); P = ex2.f16x2 (registers) ----
#pragma unroll
        for (int nt = 0; nt < 14; nt++) {
            const int sel = (nt < 7) ? 0 : 1;
            const int ci  = (nt < 7) ? nt : nt - 7;
            const uint32_t* krow = Ku + (8 * nt + g) * 20 + t;
            uint32_t b00 = krow[0], b01 = krow[4], b10 = krow[8], b11 = krow[12];
            uint32_t d0 = haddu2(r2[sel][0], cb2g[ci]);
            uint32_t d1 = haddu2(r2[sel][1], cb2g8[ci]);
            mma_f16acc(d0, d1, qa[0][0], qa[0][1], qa[0][2], qa[0][3], b00, b01);
            mma_f16acc(d0, d1, qa[1][0], qa[1][1], qa[1][2], qa[1][3], b10, b11);
            uint32_t e0 = ex2h2(d0);
            uint32_t e1 = ex2h2(d1);
            ls2g  = haddu2(ls2g,  e0);
            ls2g8 = haddu2(ls2g8, e1);
            pe0[nt] = e0;
            pe1[nt] = e1;
        }
        {
            __half2 a = *(__half2*)&ls2g, b = *(__half2*)&ls2g8;
            lsum0 += __low2float(a) + __high2float(a);
            lsum1 += __low2float(b) + __high2float(b);
        }

        // ---- O += P V : A-fragments come straight from pe0/pe1 ------------
#pragma unroll
        for (int kc = 0; kc < 7; kc++) {
            uint32_t a0 = pe0[2 * kc],     a1 = pe1[2 * kc];
            uint32_t a2 = pe0[2 * kc + 1], a3 = pe1[2 * kc + 1];
#pragma unroll
            for (int mt = 0; mt < 4; mt++) {
                const uint32_t* vrow = Vw + (8 * mt + g) * 68 + 8 * kc + t;
                mma_f16(Oa[mt][0], Oa[mt][1], Oa[mt][2], Oa[mt][3],
                        a0, a1, a2, a3, vrow[0], vrow[4]);
            }
        }
    }

    lsum0 += __shfl_xor_sync(0xffffffffu, lsum0, 1);
    lsum0 += __shfl_xor_sync(0xffffffffu, lsum0, 2);
    lsum1 += __shfl_xor_sync(0xffffffffu, lsum1, 1);
    lsum1 += __shfl_xor_sync(0xffffffffu, lsum1, 2);
    const float rinv0 = 1.0f / lsum0;
    const float rinv1 = 1.0f / lsum1;

    __syncthreads();   // mainloop done with K/V smem; reuse for epilogue

    {
        uint32_t* Os = (uint32_t*)(smc + OSOFF);
#pragma unroll
        for (int mt = 0; mt < 4; mt++) {
            uint32_t lo = pkh2(Oa[mt][0] * rinv0, Oa[mt][1] * rinv0);
            uint32_t hi = pkh2(Oa[mt][2] * rinv1, Oa[mt][3] * rinv1);
            Os[(wq0 + g)     * 20 + 4 * mt + t] = lo;
            Os[(wq0 + g + 8) * 20 + 4 * mt + t] = hi;
        }
    }
    {
        __half* Wos = (__half*)(smc + WOSOFF);
        for (int i = tid; i < 2048; i += 128) {
            int co = i >> 5, m = i & 31;
            Wos[co * 40 + m] = __float2half(Wo[co * 256 + m * 8 + h]);
        }
    }
    __syncthreads();

    {
        const int wco = w * 16;
        const uint32_t* Ww = (const uint32_t*)(smc + WOSOFF);
        const uint32_t* Os = (const uint32_t*)(smc + OSOFF);
        uint32_t wa[2][4];
#pragma unroll
        for (int kc = 0; kc < 2; kc++) {
            wa[kc][0] = Ww[(wco + g)     * 20 + 8 * kc + t];
            wa[kc][1] = Ww[(wco + g + 8) * 20 + 8 * kc + t];
            wa[kc][2] = Ww[(wco + g)     * 20 + 8 * kc + t + 4];
            wa[kc][3] = Ww[(wco + g + 8) * 20 + 8 * kc + t + 4];
        }
#pragma unroll
        for (int nt = 0; nt < 8; nt++) {
            const uint32_t* orow = Os + (8 * nt + g) * 20 + t;
            uint32_t b00 = orow[0], b01 = orow[4], b10 = orow[8], b11 = orow[12];
            float y0 = 0.f, y1 = 0.f, y2 = 0.f, y3 = 0.f;
            mma_f16(y0, y1, y2, y3, wa[0][0], wa[0][1], wa[0][2], wa[0][3], b00, b01);
            mma_f16(y0, y1, y2, y3, wa[1][0], wa[1][1], wa[1][2], wa[1][3], b10, b11);
            int co = wco + g;
            int pp = p0 + 8 * nt + 2 * t;
            atomicAdd(&out[co       * N_POS + pp],     y0);
            atomicAdd(&out[co       * N_POS + pp + 1], y1);
            atomicAdd(&out[(co + 8) * N_POS + pp],     y2);
            atomicAdd(&out[(co + 8) * N_POS + pp + 1], y3);
        }
    }
}

// ---------------- launch -----------------------------------------------------
extern "C" void kernel_launch(void* const* d_in, const int* in_sizes, int n_in,
                              void* d_out, int out_size)
{
    const float* x    = (const float*)d_in[0];
    const float* Wq   = (const float*)d_in[1];
    const float* bq   = (const float*)d_in[2];
    const float* Wk   = (const float*)d_in[3];
    const float* bk   = (const float*)d_in[4];
    const float* Wv   = (const float*)d_in[5];
    const float* bv   = (const float*)d_in[6];
    const float* Wo   = (const float*)d_in[7];
    const float* bo   = (const float*)d_in[8];
    const float* rowT = (const float*)d_in[9];
    const float* colT = (const float*)d_in[10];

    cudaFuncSetAttribute(attn_kernel,
                         cudaFuncAttributeMaxDynamicSharedMemorySize, SMEMB);

    qkv_kernel<<<dim3(49, 12), 128>>>(x, Wq, bq, Wk, bk, Wv, bv);
    bias_kernel<<<10976, 256>>>(rowT, colT);
    init_kernel<<<392, 128>>>(bo, (float*)d_out);
    attn_kernel<<<392, 128, SMEMB>>>(Wo, (float*)d_out);
}